// round 1
// baseline (speedup 1.0000x reference)
#include <cuda_runtime.h>
#include <math.h>

#define B_  2
#define S_  2048
#define D_  2048
#define H_  16
#define HD_ 128
#define M_  (B_*S_)          // 4096
#define N3_ (3*D_)           // 6144

// ---------------- scratch (device globals; no allocs allowed) ----------------
__device__ float g_qkv[(size_t)M_ * N3_];            // qkv projection output
__device__ float g_q[(size_t)(B_*H_) * S_ * HD_];    // Q (rope'd), [B,H,S,HD]
__device__ float g_k[(size_t)(B_*H_) * S_ * HD_];    // K (rope'd)
__device__ float g_v[(size_t)(B_*H_) * S_ * HD_];    // V
__device__ float g_o[(size_t)M_ * D_];               // attention out, [B,S,D]

// ---------------- fp32 SGEMM: C[M,N] = A[M,K] @ B[K,N], 128x128 tile ----------------
__global__ __launch_bounds__(256, 2)
void sgemm128(const float* __restrict__ A, const float* __restrict__ Bm,
              float* __restrict__ C, int M, int N, int K)
{
    __shared__ float As[8][128];
    __shared__ float Bs[8][128];
    const int tid = threadIdx.x;
    const int tx = tid & 15;
    const int ty = tid >> 4;
    const int arow = tid >> 1;          // 0..127
    const int acol = (tid & 1) << 2;    // 0 or 4
    const int brow = tid >> 5;          // 0..7
    const int bcol = (tid & 31) << 2;   // 0..124

    const float* Ap = A + (size_t)(blockIdx.y * 128 + arow) * K + acol;
    const float* Bp = Bm + (size_t)brow * N + blockIdx.x * 128 + bcol;

    float acc[8][8];
#pragma unroll
    for (int i = 0; i < 8; i++)
#pragma unroll
        for (int j = 0; j < 8; j++) acc[i][j] = 0.f;

    for (int k0 = 0; k0 < K; k0 += 8) {
        float4 av = *(const float4*)(Ap + k0);
        float4 bv = *(const float4*)(Bp + (size_t)k0 * N);
        __syncthreads();
        As[acol + 0][arow] = av.x;
        As[acol + 1][arow] = av.y;
        As[acol + 2][arow] = av.z;
        As[acol + 3][arow] = av.w;
        *(float4*)&Bs[brow][bcol] = bv;
        __syncthreads();
#pragma unroll
        for (int kk = 0; kk < 8; kk++) {
            float a[8], b[8];
            *(float4*)(a)     = *(const float4*)&As[kk][ty * 8];
            *(float4*)(a + 4) = *(const float4*)&As[kk][ty * 8 + 4];
            *(float4*)(b)     = *(const float4*)&Bs[kk][tx * 8];
            *(float4*)(b + 4) = *(const float4*)&Bs[kk][tx * 8 + 4];
#pragma unroll
            for (int i = 0; i < 8; i++)
#pragma unroll
                for (int j = 0; j < 8; j++) acc[i][j] += a[i] * b[j];
        }
    }
#pragma unroll
    for (int i = 0; i < 8; i++) {
        float* Cp = C + (size_t)(blockIdx.y * 128 + ty * 8 + i) * N + blockIdx.x * 128 + tx * 8;
        *(float4*)(Cp)     = make_float4(acc[i][0], acc[i][1], acc[i][2], acc[i][3]);
        *(float4*)(Cp + 4) = make_float4(acc[i][4], acc[i][5], acc[i][6], acc[i][7]);
    }
}

// ---------------- RoPE + scatter to [B,H,S,HD] ----------------
__global__ __launch_bounds__(256)
void rope_split(const float* __restrict__ qkv,
                const float* __restrict__ sinp, const float* __restrict__ cosp,
                float* __restrict__ Q, float* __restrict__ K, float* __restrict__ V)
{
    int idx = blockIdx.x * blockDim.x + threadIdx.x;   // B*S*H*64
    int hd = idx & 63;
    int h  = (idx >> 6) & 15;
    int s  = (idx >> 10) & 2047;
    int b  = idx >> 21;

    const float* row = qkv + ((size_t)b * S_ + s) * N3_ + h * HD_;
    float s1 = sinp[s * HD_ + hd],      c1 = cosp[s * HD_ + hd];
    float s2 = sinp[s * HD_ + hd + 64], c2 = cosp[s * HD_ + hd + 64];
    size_t ob = ((size_t)(b * H_ + h) * S_ + s) * HD_ + hd;
    {
        float x1 = row[hd], x2 = row[hd + 64];
        Q[ob]      = x1 * c1 - x2 * s1;
        Q[ob + 64] = x2 * c2 + x1 * s2;
    }
    {
        float x1 = row[D_ + hd], x2 = row[D_ + hd + 64];
        K[ob]      = x1 * c1 - x2 * s1;
        K[ob + 64] = x2 * c2 + x1 * s2;
    }
    V[ob]      = row[2 * D_ + hd];
    V[ob + 64] = row[2 * D_ + hd + 64];
}

// ---------------- causal flash attention, BM=BN=64, HD=128, fp32 ----------------
#define ATTN_SMEM_FLOATS (128*68 + 128*68 + 64*128 + 64*67 + 192)

__global__ __launch_bounds__(256, 1)
void attn_kernel(const float* __restrict__ Q, const float* __restrict__ K,
                 const float* __restrict__ V, float* __restrict__ O)
{
    extern __shared__ float sm[];
    float* QT   = sm;                   // [128][68] transposed Q tile
    float* KT   = QT + 128 * 68;        // [128][68] transposed K tile
    float* Vs   = KT + 128 * 68;        // [64][128] natural V tile
    float* Ps   = Vs + 64 * 128;        // [64][67]  probs tile
    float* m_s  = Ps + 64 * 67;
    float* l_s  = m_s + 64;
    float* sc_s = l_s + 64;

    const int tid = threadIdx.x;
    const int tx = tid & 15, ty = tid >> 4;
    const int bh = blockIdx.y;          // 0..31
    const int iq = blockIdx.x;          // 0..31  (query tile)
    const float* Qb = Q + ((size_t)bh * S_ + iq * 64) * HD_;
    const float* Kb = K + (size_t)bh * S_ * HD_;
    const float* Vb = V + (size_t)bh * S_ * HD_;

    // load Q tile transposed
#pragma unroll
    for (int i = tid; i < 64 * 32; i += 256) {
        int r = i >> 5, c4 = (i & 31) << 2;
        float4 v = *(const float4*)(Qb + (size_t)r * HD_ + c4);
        QT[(c4 + 0) * 68 + r] = v.x;
        QT[(c4 + 1) * 68 + r] = v.y;
        QT[(c4 + 2) * 68 + r] = v.z;
        QT[(c4 + 3) * 68 + r] = v.w;
    }
    if (tid < 64) { m_s[tid] = -1e30f; l_s[tid] = 0.f; }

    float o[4][8];
#pragma unroll
    for (int i = 0; i < 4; i++)
#pragma unroll
        for (int j = 0; j < 8; j++) o[i][j] = 0.f;

    const int r0 = ty * 4, c0 = tx * 8;
    const float scale = 0.08838834764831845f;   // 1/sqrt(128)

    for (int kt = 0; kt <= iq; kt++) {
        __syncthreads();   // prior PV done reading Vs/Ps
        const float* Kt = Kb + (size_t)kt * 64 * HD_;
        const float* Vt = Vb + (size_t)kt * 64 * HD_;
#pragma unroll
        for (int i = tid; i < 64 * 32; i += 256) {
            int r = i >> 5, c4 = (i & 31) << 2;
            float4 kv = *(const float4*)(Kt + (size_t)r * HD_ + c4);
            KT[(c4 + 0) * 68 + r] = kv.x;
            KT[(c4 + 1) * 68 + r] = kv.y;
            KT[(c4 + 2) * 68 + r] = kv.z;
            KT[(c4 + 3) * 68 + r] = kv.w;
            float4 vv = *(const float4*)(Vt + (size_t)r * HD_ + c4);
            *(float4*)&Vs[r * 128 + c4] = vv;
        }
        __syncthreads();

        // S = Q K^T  (each thread 4x4)
        float s[4][4];
#pragma unroll
        for (int i = 0; i < 4; i++)
#pragma unroll
            for (int j = 0; j < 4; j++) s[i][j] = 0.f;

        for (int kk = 0; kk < 128; kk++) {
            float4 a = *(const float4*)&QT[kk * 68 + r0];
            float4 b = *(const float4*)&KT[kk * 68 + tx * 4];
            float av[4] = {a.x, a.y, a.z, a.w};
            float bv[4] = {b.x, b.y, b.z, b.w};
#pragma unroll
            for (int i = 0; i < 4; i++)
#pragma unroll
                for (int j = 0; j < 4; j++) s[i][j] += av[i] * bv[j];
        }

        const bool diag = (kt == iq);
#pragma unroll
        for (int i = 0; i < 4; i++)
#pragma unroll
            for (int j = 0; j < 4; j++) {
                float val = s[i][j] * scale;
                int col = tx * 4 + j, row = r0 + i;
                if (diag && col > row) val = -1e30f;
                Ps[row * 67 + col] = val;
            }
        __syncthreads();

        // online softmax, one thread per row
        if (tid < 64) {
            int r = tid;
            float mloc = -1e30f;
            for (int c = 0; c < 64; c++) mloc = fmaxf(mloc, Ps[r * 67 + c]);
            float mnew = fmaxf(m_s[r], mloc);
            float sc = __expf(m_s[r] - mnew);
            float lsum = 0.f;
            for (int c = 0; c < 64; c++) {
                float p = __expf(Ps[r * 67 + c] - mnew);
                Ps[r * 67 + c] = p;
                lsum += p;
            }
            l_s[r] = l_s[r] * sc + lsum;
            m_s[r] = mnew;
            sc_s[r] = sc;
        }
        __syncthreads();

        // rescale accumulators, then O += P @ V
        float f0 = sc_s[r0], f1 = sc_s[r0 + 1], f2 = sc_s[r0 + 2], f3 = sc_s[r0 + 3];
#pragma unroll
        for (int j = 0; j < 8; j++) {
            o[0][j] *= f0; o[1][j] *= f1; o[2][j] *= f2; o[3][j] *= f3;
        }
        for (int kk = 0; kk < 64; kk++) {
            float4 v0 = *(const float4*)&Vs[kk * 128 + c0];
            float4 v1 = *(const float4*)&Vs[kk * 128 + c0 + 4];
            float vv[8] = {v0.x, v0.y, v0.z, v0.w, v1.x, v1.y, v1.z, v1.w};
#pragma unroll
            for (int i = 0; i < 4; i++) {
                float p = Ps[(r0 + i) * 67 + kk];
#pragma unroll
                for (int j = 0; j < 8; j++) o[i][j] += p * vv[j];
            }
        }
    }

    // epilogue: divide by l, write [B,S,D]
    int b = bh >> 4, h = bh & 15;
#pragma unroll
    for (int i = 0; i < 4; i++) {
        float inv = 1.f / l_s[r0 + i];
        float* Op = O + ((size_t)(b * S_ + iq * 64 + r0 + i)) * D_ + h * HD_ + c0;
        *(float4*)(Op)     = make_float4(o[i][0] * inv, o[i][1] * inv, o[i][2] * inv, o[i][3] * inv);
        *(float4*)(Op + 4) = make_float4(o[i][4] * inv, o[i][5] * inv, o[i][6] * inv, o[i][7] * inv);
    }
}

// ---------------- launch ----------------
extern "C" void kernel_launch(void* const* d_in, const int* in_sizes, int n_in,
                              void* d_out, int out_size)
{
    const float* x     = (const float*)d_in[0];
    // d_in[1] = mask (causal tril, handled analytically)
    const float* sinp  = (const float*)d_in[2];
    const float* cosp  = (const float*)d_in[3];
    const float* Wqkv  = (const float*)d_in[4];
    const float* Wproj = (const float*)d_in[5];
    float* out = (float*)d_out;

    float *qkv, *q, *k, *v, *o;
    cudaGetSymbolAddress((void**)&qkv, g_qkv);
    cudaGetSymbolAddress((void**)&q,   g_q);
    cudaGetSymbolAddress((void**)&k,   g_k);
    cudaGetSymbolAddress((void**)&v,   g_v);
    cudaGetSymbolAddress((void**)&o,   g_o);

    const int attn_smem = ATTN_SMEM_FLOATS * (int)sizeof(float);
    cudaFuncSetAttribute(attn_kernel, cudaFuncAttributeMaxDynamicSharedMemorySize, attn_smem);

    // 1) QKV projection: [4096,2048] @ [2048,6144]
    {
        dim3 g(N3_ / 128, M_ / 128);
        sgemm128<<<g, 256>>>(x, Wqkv, qkv, M_, N3_, D_);
    }
    // 2) RoPE + head-major scatter
    {
        int total = B_ * S_ * H_ * 64;
        rope_split<<<total / 256, 256>>>(qkv, sinp, cosp, q, k, v);
    }
    // 3) causal flash attention
    {
        dim3 g(S_ / 64, B_ * H_);
        attn_kernel<<<g, 256, attn_smem>>>(q, k, v, o);
    }
    // 4) output projection: [4096,2048] @ [2048,2048]
    {
        dim3 g(D_ / 128, M_ / 128);
        sgemm128<<<g, 256>>>(o, Wproj, out, M_, D_, D_);
    }
}

// round 3
// speedup vs baseline: 1.5639x; 1.5639x over previous
#include <cuda_runtime.h>
#include <cuda_bf16.h>
#include <math.h>
#include <stdint.h>

#define B_  2
#define S_  2048
#define D_  2048
#define H_  16
#define HD_ 128
#define M_  (B_*S_)          // 4096
#define N3_ (3*D_)           // 6144
#define K_  D_               // 2048

// ---------------- scratch (device globals; no allocs allowed) ----------------
__device__ float g_qkv[(size_t)M_ * N3_];            // qkv projection output
__device__ float g_q[(size_t)(B_*H_) * S_ * HD_];    // Q (rope'd), [B,H,S,HD]
__device__ float g_k[(size_t)(B_*H_) * S_ * HD_];    // K (rope'd)
__device__ float g_v[(size_t)(B_*H_) * S_ * HD_];    // V
__device__ float g_o[(size_t)M_ * D_];               // attention out, [B,S,D]
__device__ __nv_bfloat16 g_ahi[(size_t)M_ * K_];     // A operand hi (x, then attn out)
__device__ __nv_bfloat16 g_alo[(size_t)M_ * K_];     // A operand lo
__device__ __nv_bfloat16 g_bhi[(size_t)N3_ * K_];    // B operand hi, [N,K] (transposed W)
__device__ __nv_bfloat16 g_blo[(size_t)N3_ * K_];    // B operand lo

// ================= helpers =================
__device__ __forceinline__ uint32_t smem_u32(const void* p) {
    uint32_t a;
    asm("{ .reg .u64 t; cvta.to.shared.u64 t, %1; cvt.u32.u64 %0, t; }" : "=r"(a) : "l"(p));
    return a;
}
#define CP_ASYNC16(sm_addr, gptr) \
    asm volatile("cp.async.cg.shared.global [%0], [%1], 16;" :: "r"(sm_addr), "l"(gptr))
#define CP_COMMIT() asm volatile("cp.async.commit_group;" ::: "memory")
#define CP_WAIT1()  asm volatile("cp.async.wait_group 1;" ::: "memory")

#define LDSM_X4(r0, r1, r2, r3, addr) \
    asm volatile("ldmatrix.sync.aligned.m8n8.x4.shared.b16 {%0,%1,%2,%3}, [%4];" \
        : "=r"(r0), "=r"(r1), "=r"(r2), "=r"(r3) : "r"(addr))

#define MMA16816(d, a, b) \
    asm volatile("mma.sync.aligned.m16n8k16.row.col.f32.bf16.bf16.f32 " \
        "{%0,%1,%2,%3}, {%4,%5,%6,%7}, {%8,%9}, {%0,%1,%2,%3};" \
        : "+f"((d)[0]), "+f"((d)[1]), "+f"((d)[2]), "+f"((d)[3]) \
        : "r"((a)[0]), "r"((a)[1]), "r"((a)[2]), "r"((a)[3]), "r"((b)[0]), "r"((b)[1]))

// ================= HMMA GEMM: C[M,N] = (Ahi+Alo)[M,K] @ (Bhi+Blo)[N,K]^T =================
// CTA tile 128x128, 8 warps (4M x 2N), warp tile 32x64, KC=32, double buffered.
#define KC 32
#define ASTRIDE 40                    // bf16 elems per smem row (32 data + 8 pad) = 80 B
#define ATILE_B (128 * ASTRIDE * 2)   // 10240 B per tile
#define STAGE_B (4 * ATILE_B)         // Ahi|Alo|Bhi|Blo = 40960 B
#define GEMM_SMEM (2 * STAGE_B)       // 81920 B

__device__ __forceinline__ void load_chunk_mma(
    uint32_t base, const __nv_bfloat16* Ahi, const __nv_bfloat16* Alo,
    const __nv_bfloat16* Bhi, const __nv_bfloat16* Blo,
    int m0, int n0, int k0, int K, int tid)
{
    for (int i = tid; i < 512; i += 256) {
        int r = i >> 2, g = i & 3;
        uint32_t so = (uint32_t)(r * 80 + g * 16);
        const __nv_bfloat16* a0 = Ahi + (size_t)(m0 + r) * K + k0 + g * 8;
        const __nv_bfloat16* a1 = Alo + (size_t)(m0 + r) * K + k0 + g * 8;
        const __nv_bfloat16* b0 = Bhi + (size_t)(n0 + r) * K + k0 + g * 8;
        const __nv_bfloat16* b1 = Blo + (size_t)(n0 + r) * K + k0 + g * 8;
        CP_ASYNC16(base + so,               a0);
        CP_ASYNC16(base + ATILE_B + so,     a1);
        CP_ASYNC16(base + 2 * ATILE_B + so, b0);
        CP_ASYNC16(base + 3 * ATILE_B + so, b1);
    }
}

__global__ __launch_bounds__(256)
void gemm_mma(const __nv_bfloat16* __restrict__ Ahi, const __nv_bfloat16* __restrict__ Alo,
              const __nv_bfloat16* __restrict__ Bhi, const __nv_bfloat16* __restrict__ Blo,
              float* __restrict__ C, int N, int K)
{
    extern __shared__ char sm[];
    const uint32_t smb = smem_u32(sm);
    const int tid = threadIdx.x;
    const int wid = tid >> 5;
    const int lane = tid & 31;
    const int wm = wid & 3;           // warp row (4 along M)
    const int wn = wid >> 2;          // warp col (2 along N)
    const int m0 = blockIdx.y * 128;
    const int n0 = blockIdx.x * 128;

    const uint32_t stg0 = smb;
    const uint32_t stg1 = smb + STAGE_B;

    float acc[2][8][4];
#pragma unroll
    for (int i = 0; i < 2; i++)
#pragma unroll
        for (int j = 0; j < 8; j++)
#pragma unroll
            for (int t = 0; t < 4; t++) acc[i][j][t] = 0.f;

    // prologue: fill both stages
    load_chunk_mma(stg0, Ahi, Alo, Bhi, Blo, m0, n0, 0, K, tid);
    CP_COMMIT();
    load_chunk_mma(stg1, Ahi, Alo, Bhi, Blo, m0, n0, KC, K, tid);
    CP_COMMIT();

    const int NC = K / KC;            // 64
    // per-lane ldmatrix row offsets
    const int lrow = lane & 15;       // row within 16
    const int lcol = (lane >> 4) * 16;  // 0 or 16 bytes (k half)

    for (int c = 0; c < NC; c++) {
        const uint32_t base = (c & 1) ? stg1 : stg0;
        CP_WAIT1();
        __syncthreads();

        const uint32_t sA[2] = { base, base + ATILE_B };
        const uint32_t sB[2] = { base + 2 * ATILE_B, base + 3 * ATILE_B };
        const int pa[3] = {0, 0, 1};
        const int pb[3] = {0, 1, 0};

#pragma unroll
        for (int p = 0; p < 3; p++) {
#pragma unroll
            for (int ks = 0; ks < 2; ks++) {
                uint32_t a[2][4], b[8][2];
#pragma unroll
                for (int mt = 0; mt < 2; mt++) {
                    uint32_t addr = sA[pa[p]] +
                        (uint32_t)((wm * 32 + mt * 16 + lrow) * 80 + ks * 32 + lcol);
                    LDSM_X4(a[mt][0], a[mt][1], a[mt][2], a[mt][3], addr);
                }
#pragma unroll
                for (int nb = 0; nb < 4; nb++) {
                    uint32_t r0, r1, r2, r3;
                    uint32_t addr = sB[pb[p]] +
                        (uint32_t)((wn * 64 + nb * 16 + lrow) * 80 + ks * 32 + lcol);
                    LDSM_X4(r0, r1, r2, r3, addr);
                    b[2 * nb][0] = r0; b[2 * nb][1] = r2;
                    b[2 * nb + 1][0] = r1; b[2 * nb + 1][1] = r3;
                }
#pragma unroll
                for (int mt = 0; mt < 2; mt++)
#pragma unroll
                    for (int nt = 0; nt < 8; nt++)
                        MMA16816(acc[mt][nt], a[mt], b[nt]);
            }
        }
        __syncthreads();
        if (c + 2 < NC) {
            load_chunk_mma(base, Ahi, Alo, Bhi, Blo, m0, n0, (c + 2) * KC, K, tid);
        }
        CP_COMMIT();
    }

    // epilogue: c fragment -> C. thread t: rows groupID=(t/4), cols (t%4)*2
    const int grow = lane >> 2;
    const int gcol = (lane & 3) * 2;
#pragma unroll
    for (int mt = 0; mt < 2; mt++) {
        int row = m0 + wm * 32 + mt * 16 + grow;
#pragma unroll
        for (int nt = 0; nt < 8; nt++) {
            int col = n0 + wn * 64 + nt * 8 + gcol;
            float* c0 = C + (size_t)row * N + col;
            float* c1 = C + (size_t)(row + 8) * N + col;
            c0[0] = acc[mt][nt][0]; c0[1] = acc[mt][nt][1];
            c1[0] = acc[mt][nt][2]; c1[1] = acc[mt][nt][3];
        }
    }
}

// ================= conversion kernels =================
__global__ __launch_bounds__(256)
void conv_split(const float* __restrict__ A, __nv_bfloat16* __restrict__ hi,
                __nv_bfloat16* __restrict__ lo, int n4)
{
    int i = blockIdx.x * blockDim.x + threadIdx.x;
    if (i >= n4) return;
    float4 v = ((const float4*)A)[i];
    __nv_bfloat16 h[4], l[4];
    float vv[4] = {v.x, v.y, v.z, v.w};
#pragma unroll
    for (int j = 0; j < 4; j++) {
        h[j] = __float2bfloat16(vv[j]);
        l[j] = __float2bfloat16(vv[j] - __bfloat162float(h[j]));
    }
    ((uint2*)hi)[i] = *(uint2*)h;
    ((uint2*)lo)[i] = *(uint2*)l;
}

// W[K,N] fp32 -> Bt[N,K] bf16 hi/lo (transpose + split), 32x32 tiles
__global__ __launch_bounds__(256)
void conv_w_t(const float* __restrict__ W, __nv_bfloat16* __restrict__ hi,
              __nv_bfloat16* __restrict__ lo, int K, int N)
{
    __shared__ float t[32][33];
    const int tx = threadIdx.x & 31;
    const int ty = threadIdx.x >> 5;      // 0..7
    const int n0 = blockIdx.x * 32;
    const int k0 = blockIdx.y * 32;
#pragma unroll
    for (int j = 0; j < 4; j++)
        t[ty + j * 8][tx] = W[(size_t)(k0 + ty + j * 8) * N + n0 + tx];
    __syncthreads();
#pragma unroll
    for (int j = 0; j < 4; j++) {
        int r = ty + j * 8;               // local n
        float v = t[tx][r];
        __nv_bfloat16 h = __float2bfloat16(v);
        __nv_bfloat16 l = __float2bfloat16(v - __bfloat162float(h));
        size_t o = (size_t)(n0 + r) * K + k0 + tx;
        hi[o] = h;
        lo[o] = l;
    }
}

// ---------------- RoPE + scatter to [B,H,S,HD] ----------------
__global__ __launch_bounds__(256)
void rope_split(const float* __restrict__ qkv,
                const float* __restrict__ sinp, const float* __restrict__ cosp,
                float* __restrict__ Q, float* __restrict__ K, float* __restrict__ V)
{
    int idx = blockIdx.x * blockDim.x + threadIdx.x;   // B*S*H*64
    int hd = idx & 63;
    int h  = (idx >> 6) & 15;
    int s  = (idx >> 10) & 2047;
    int b  = idx >> 21;

    const float* row = qkv + ((size_t)b * S_ + s) * N3_ + h * HD_;
    float s1 = sinp[s * HD_ + hd],      c1 = cosp[s * HD_ + hd];
    float s2 = sinp[s * HD_ + hd + 64], c2 = cosp[s * HD_ + hd + 64];
    size_t ob = ((size_t)(b * H_ + h) * S_ + s) * HD_ + hd;
    {
        float x1 = row[hd], x2 = row[hd + 64];
        Q[ob]      = x1 * c1 - x2 * s1;
        Q[ob + 64] = x2 * c2 + x1 * s2;
    }
    {
        float x1 = row[D_ + hd], x2 = row[D_ + hd + 64];
        K[ob]      = x1 * c1 - x2 * s1;
        K[ob + 64] = x2 * c2 + x1 * s2;
    }
    V[ob]      = row[2 * D_ + hd];
    V[ob + 64] = row[2 * D_ + hd + 64];
}

// ---------------- causal flash attention, BM=BN=64, HD=128, fp32 ----------------
#define ATTN_SMEM_FLOATS (128*68 + 128*68 + 64*128 + 64*67 + 192)

__global__ __launch_bounds__(256, 1)
void attn_kernel(const float* __restrict__ Q, const float* __restrict__ K,
                 const float* __restrict__ V, float* __restrict__ O)
{
    extern __shared__ float smf[];
    float* QT   = smf;                  // [128][68] transposed Q tile
    float* KT   = QT + 128 * 68;        // [128][68] transposed K tile
    float* Vs   = KT + 128 * 68;        // [64][128] natural V tile
    float* Ps   = Vs + 64 * 128;        // [64][67]  probs tile
    float* m_s  = Ps + 64 * 67;
    float* l_s  = m_s + 64;
    float* sc_s = l_s + 64;

    const int tid = threadIdx.x;
    const int tx = tid & 15, ty = tid >> 4;
    const int bh = blockIdx.y;          // 0..31
    const int iq = blockIdx.x;          // 0..31  (query tile)
    const float* Qb = Q + ((size_t)bh * S_ + iq * 64) * HD_;
    const float* Kb = K + (size_t)bh * S_ * HD_;
    const float* Vb = V + (size_t)bh * S_ * HD_;

#pragma unroll
    for (int i = tid; i < 64 * 32; i += 256) {
        int r = i >> 5, c4 = (i & 31) << 2;
        float4 v = *(const float4*)(Qb + (size_t)r * HD_ + c4);
        QT[(c4 + 0) * 68 + r] = v.x;
        QT[(c4 + 1) * 68 + r] = v.y;
        QT[(c4 + 2) * 68 + r] = v.z;
        QT[(c4 + 3) * 68 + r] = v.w;
    }
    if (tid < 64) { m_s[tid] = -1e30f; l_s[tid] = 0.f; }

    float o[4][8];
#pragma unroll
    for (int i = 0; i < 4; i++)
#pragma unroll
        for (int j = 0; j < 8; j++) o[i][j] = 0.f;

    const int r0 = ty * 4, c0 = tx * 8;
    const float scale = 0.08838834764831845f;   // 1/sqrt(128)

    for (int kt = 0; kt <= iq; kt++) {
        __syncthreads();
        const float* Kt = Kb + (size_t)kt * 64 * HD_;
        const float* Vt = Vb + (size_t)kt * 64 * HD_;
#pragma unroll
        for (int i = tid; i < 64 * 32; i += 256) {
            int r = i >> 5, c4 = (i & 31) << 2;
            float4 kv = *(const float4*)(Kt + (size_t)r * HD_ + c4);
            KT[(c4 + 0) * 68 + r] = kv.x;
            KT[(c4 + 1) * 68 + r] = kv.y;
            KT[(c4 + 2) * 68 + r] = kv.z;
            KT[(c4 + 3) * 68 + r] = kv.w;
            float4 vv = *(const float4*)(Vt + (size_t)r * HD_ + c4);
            *(float4*)&Vs[r * 128 + c4] = vv;
        }
        __syncthreads();

        float s[4][4];
#pragma unroll
        for (int i = 0; i < 4; i++)
#pragma unroll
            for (int j = 0; j < 4; j++) s[i][j] = 0.f;

        for (int kk = 0; kk < 128; kk++) {
            float4 a = *(const float4*)&QT[kk * 68 + r0];
            float4 b = *(const float4*)&KT[kk * 68 + tx * 4];
            float av[4] = {a.x, a.y, a.z, a.w};
            float bv[4] = {b.x, b.y, b.z, b.w};
#pragma unroll
            for (int i = 0; i < 4; i++)
#pragma unroll
                for (int j = 0; j < 4; j++) s[i][j] += av[i] * bv[j];
        }

        const bool diag = (kt == iq);
#pragma unroll
        for (int i = 0; i < 4; i++)
#pragma unroll
            for (int j = 0; j < 4; j++) {
                float val = s[i][j] * scale;
                int col = tx * 4 + j, row = r0 + i;
                if (diag && col > row) val = -1e30f;
                Ps[row * 67 + col] = val;
            }
        __syncthreads();

        if (tid < 64) {
            int r = tid;
            float mloc = -1e30f;
            for (int c = 0; c < 64; c++) mloc = fmaxf(mloc, Ps[r * 67 + c]);
            float mnew = fmaxf(m_s[r], mloc);
            float sc = __expf(m_s[r] - mnew);
            float lsum = 0.f;
            for (int c = 0; c < 64; c++) {
                float p = __expf(Ps[r * 67 + c] - mnew);
                Ps[r * 67 + c] = p;
                lsum += p;
            }
            l_s[r] = l_s[r] * sc + lsum;
            m_s[r] = mnew;
            sc_s[r] = sc;
        }
        __syncthreads();

        float f0 = sc_s[r0], f1 = sc_s[r0 + 1], f2 = sc_s[r0 + 2], f3 = sc_s[r0 + 3];
#pragma unroll
        for (int j = 0; j < 8; j++) {
            o[0][j] *= f0; o[1][j] *= f1; o[2][j] *= f2; o[3][j] *= f3;
        }
        for (int kk = 0; kk < 64; kk++) {
            float4 v0 = *(const float4*)&Vs[kk * 128 + c0];
            float4 v1 = *(const float4*)&Vs[kk * 128 + c0 + 4];
            float vv[8] = {v0.x, v0.y, v0.z, v0.w, v1.x, v1.y, v1.z, v1.w};
#pragma unroll
            for (int i = 0; i < 4; i++) {
                float p = Ps[(r0 + i) * 67 + kk];
#pragma unroll
                for (int j = 0; j < 8; j++) o[i][j] += p * vv[j];
            }
        }
    }

    int b = bh >> 4, h = bh & 15;
#pragma unroll
    for (int i = 0; i < 4; i++) {
        float inv = 1.f / l_s[r0 + i];
        float* Op = O + ((size_t)(b * S_ + iq * 64 + r0 + i)) * D_ + h * HD_ + c0;
        *(float4*)(Op)     = make_float4(o[i][0] * inv, o[i][1] * inv, o[i][2] * inv, o[i][3] * inv);
        *(float4*)(Op + 4) = make_float4(o[i][4] * inv, o[i][5] * inv, o[i][6] * inv, o[i][7] * inv);
    }
}

// ---------------- launch ----------------
extern "C" void kernel_launch(void* const* d_in, const int* in_sizes, int n_in,
                              void* d_out, int out_size)
{
    const float* x     = (const float*)d_in[0];
    // d_in[1] = mask (causal tril, handled analytically)
    const float* sinp  = (const float*)d_in[2];
    const float* cosp  = (const float*)d_in[3];
    const float* Wqkv  = (const float*)d_in[4];
    const float* Wproj = (const float*)d_in[5];
    float* out = (float*)d_out;

    float *qkv, *q, *k, *v, *o;
    __nv_bfloat16 *ahi, *alo, *bhi, *blo;
    cudaGetSymbolAddress((void**)&qkv, g_qkv);
    cudaGetSymbolAddress((void**)&q,   g_q);
    cudaGetSymbolAddress((void**)&k,   g_k);
    cudaGetSymbolAddress((void**)&v,   g_v);
    cudaGetSymbolAddress((void**)&o,   g_o);
    cudaGetSymbolAddress((void**)&ahi, g_ahi);
    cudaGetSymbolAddress((void**)&alo, g_alo);
    cudaGetSymbolAddress((void**)&bhi, g_bhi);
    cudaGetSymbolAddress((void**)&blo, g_blo);

    const int attn_smem = ATTN_SMEM_FLOATS * (int)sizeof(float);
    cudaFuncSetAttribute(attn_kernel, cudaFuncAttributeMaxDynamicSharedMemorySize, attn_smem);
    cudaFuncSetAttribute(gemm_mma, cudaFuncAttributeMaxDynamicSharedMemorySize, GEMM_SMEM);

    // 1) convert x -> bf16 hi/lo, Wqkv -> transposed bf16 hi/lo
    conv_split<<<(M_ * K_ / 4 + 255) / 256, 256>>>(x, ahi, alo, M_ * K_ / 4);
    conv_w_t<<<dim3(N3_ / 32, K_ / 32), 256>>>(Wqkv, bhi, blo, K_, N3_);

    // 2) QKV projection on tensor cores: [4096,2048] @ [2048,6144]
    gemm_mma<<<dim3(N3_ / 128, M_ / 128), 256, GEMM_SMEM>>>(ahi, alo, bhi, blo, qkv, N3_, K_);

    // 3) RoPE + head-major scatter
    rope_split<<<B_ * S_ * H_ * 64 / 256, 256>>>(qkv, sinp, cosp, q, k, v);

    // 4) causal flash attention
    attn_kernel<<<dim3(S_ / 64, B_ * H_), 256, attn_smem>>>(q, k, v, o);

    // 5) convert attention output + Wproj, then output projection
    conv_split<<<(M_ * K_ / 4 + 255) / 256, 256>>>(o, ahi, alo, M_ * K_ / 4);
    conv_w_t<<<dim3(D_ / 32, K_ / 32), 256>>>(Wproj, bhi, blo, K_, D_);
    gemm_mma<<<dim3(D_ / 128, M_ / 128), 256, GEMM_SMEM>>>(ahi, alo, bhi, blo, out, D_, K_);
}

// round 4
// speedup vs baseline: 2.4814x; 1.5867x over previous
#include <cuda_runtime.h>
#include <cuda_bf16.h>
#include <math.h>
#include <stdint.h>

#define B_  2
#define S_  2048
#define D_  2048
#define H_  16
#define HD_ 128
#define M_  (B_*S_)          // 4096
#define N3_ (3*D_)           // 6144
#define K_  D_               // 2048

// ---------------- scratch (device globals; no allocs allowed) ----------------
__device__ float g_qkv[(size_t)M_ * N3_];            // qkv projection output (fp32)
__device__ float g_o[(size_t)M_ * D_];               // attention out, [B,S,D] fp32
__device__ __nv_bfloat16 g_ahi[(size_t)M_ * K_];     // GEMM A hi (x, then attn out)
__device__ __nv_bfloat16 g_alo[(size_t)M_ * K_];     // GEMM A lo
__device__ __nv_bfloat16 g_bhi[(size_t)N3_ * K_];    // GEMM B hi, [N,K]
__device__ __nv_bfloat16 g_blo[(size_t)N3_ * K_];    // GEMM B lo
// attention operands, [B*H][S][HD] bf16 hi/lo
__device__ __nv_bfloat16 g_qhi[(size_t)(B_*H_) * S_ * HD_];
__device__ __nv_bfloat16 g_qlo[(size_t)(B_*H_) * S_ * HD_];
__device__ __nv_bfloat16 g_khi[(size_t)(B_*H_) * S_ * HD_];
__device__ __nv_bfloat16 g_klo[(size_t)(B_*H_) * S_ * HD_];
__device__ __nv_bfloat16 g_vhi[(size_t)(B_*H_) * S_ * HD_];
__device__ __nv_bfloat16 g_vlo[(size_t)(B_*H_) * S_ * HD_];

// ================= helpers =================
__device__ __forceinline__ uint32_t smem_u32(const void* p) {
    uint32_t a;
    asm("{ .reg .u64 t; cvta.to.shared.u64 t, %1; cvt.u32.u64 %0, t; }" : "=r"(a) : "l"(p));
    return a;
}
#define CP_ASYNC16(sm_addr, gptr) \
    asm volatile("cp.async.cg.shared.global [%0], [%1], 16;" :: "r"(sm_addr), "l"(gptr))
#define CP_COMMIT() asm volatile("cp.async.commit_group;" ::: "memory")
#define CP_WAIT1()  asm volatile("cp.async.wait_group 1;" ::: "memory")

#define LDSM_X4(r0, r1, r2, r3, addr) \
    asm volatile("ldmatrix.sync.aligned.m8n8.x4.shared.b16 {%0,%1,%2,%3}, [%4];" \
        : "=r"(r0), "=r"(r1), "=r"(r2), "=r"(r3) : "r"(addr))
#define LDSM_X4_T(r0, r1, r2, r3, addr) \
    asm volatile("ldmatrix.sync.aligned.m8n8.x4.trans.shared.b16 {%0,%1,%2,%3}, [%4];" \
        : "=r"(r0), "=r"(r1), "=r"(r2), "=r"(r3) : "r"(addr))

#define MMA16816(d, a, b) \
    asm volatile("mma.sync.aligned.m16n8k16.row.col.f32.bf16.bf16.f32 " \
        "{%0,%1,%2,%3}, {%4,%5,%6,%7}, {%8,%9}, {%0,%1,%2,%3};" \
        : "+f"((d)[0]), "+f"((d)[1]), "+f"((d)[2]), "+f"((d)[3]) \
        : "r"((a)[0]), "r"((a)[1]), "r"((a)[2]), "r"((a)[3]), "r"((b)[0]), "r"((b)[1]))

__device__ __forceinline__ float ex2f(float x) {
    float y;
    asm("ex2.approx.f32 %0, %1;" : "=f"(y) : "f"(x));
    return y;
}
__device__ __forceinline__ uint32_t pack_bf16(float a, float b) {
    __nv_bfloat162 t = __floats2bfloat162_rn(a, b);
    return *(uint32_t*)&t;
}

// ================= HMMA GEMM: C[M,N] = (Ahi+Alo)[M,K] @ (Bhi+Blo)[N,K]^T =================
#define KC 32
#define ASTRIDE 40
#define ATILE_B (128 * ASTRIDE * 2)   // 10240 B per tile
#define STAGE_B (4 * ATILE_B)         // 40960 B
#define GEMM_SMEM (2 * STAGE_B)       // 81920 B

__device__ __forceinline__ void load_chunk_mma(
    uint32_t base, const __nv_bfloat16* Ahi, const __nv_bfloat16* Alo,
    const __nv_bfloat16* Bhi, const __nv_bfloat16* Blo,
    int m0, int n0, int k0, int K, int tid)
{
    for (int i = tid; i < 512; i += 256) {
        int r = i >> 2, g = i & 3;
        uint32_t so = (uint32_t)(r * 80 + g * 16);
        const __nv_bfloat16* a0 = Ahi + (size_t)(m0 + r) * K + k0 + g * 8;
        const __nv_bfloat16* a1 = Alo + (size_t)(m0 + r) * K + k0 + g * 8;
        const __nv_bfloat16* b0 = Bhi + (size_t)(n0 + r) * K + k0 + g * 8;
        const __nv_bfloat16* b1 = Blo + (size_t)(n0 + r) * K + k0 + g * 8;
        CP_ASYNC16(base + so,               a0);
        CP_ASYNC16(base + ATILE_B + so,     a1);
        CP_ASYNC16(base + 2 * ATILE_B + so, b0);
        CP_ASYNC16(base + 3 * ATILE_B + so, b1);
    }
}

__global__ __launch_bounds__(256)
void gemm_mma(const __nv_bfloat16* __restrict__ Ahi, const __nv_bfloat16* __restrict__ Alo,
              const __nv_bfloat16* __restrict__ Bhi, const __nv_bfloat16* __restrict__ Blo,
              float* __restrict__ C, int N, int K)
{
    extern __shared__ char sm[];
    const uint32_t smb = smem_u32(sm);
    const int tid = threadIdx.x;
    const int wid = tid >> 5;
    const int lane = tid & 31;
    const int wm = wid & 3;
    const int wn = wid >> 2;
    const int m0 = blockIdx.y * 128;
    const int n0 = blockIdx.x * 128;

    const uint32_t stg0 = smb;
    const uint32_t stg1 = smb + STAGE_B;

    float acc[2][8][4];
#pragma unroll
    for (int i = 0; i < 2; i++)
#pragma unroll
        for (int j = 0; j < 8; j++)
#pragma unroll
            for (int t = 0; t < 4; t++) acc[i][j][t] = 0.f;

    load_chunk_mma(stg0, Ahi, Alo, Bhi, Blo, m0, n0, 0, K, tid);
    CP_COMMIT();
    load_chunk_mma(stg1, Ahi, Alo, Bhi, Blo, m0, n0, KC, K, tid);
    CP_COMMIT();

    const int NC = K / KC;
    const int lrow = lane & 15;
    const int lcol = (lane >> 4) * 16;

    for (int c = 0; c < NC; c++) {
        const uint32_t base = (c & 1) ? stg1 : stg0;
        CP_WAIT1();
        __syncthreads();

        const uint32_t sA[2] = { base, base + ATILE_B };
        const uint32_t sB[2] = { base + 2 * ATILE_B, base + 3 * ATILE_B };
        const int pa[3] = {0, 0, 1};
        const int pb[3] = {0, 1, 0};

#pragma unroll
        for (int p = 0; p < 3; p++) {
#pragma unroll
            for (int ks = 0; ks < 2; ks++) {
                uint32_t a[2][4], b[8][2];
#pragma unroll
                for (int mt = 0; mt < 2; mt++) {
                    uint32_t addr = sA[pa[p]] +
                        (uint32_t)((wm * 32 + mt * 16 + lrow) * 80 + ks * 32 + lcol);
                    LDSM_X4(a[mt][0], a[mt][1], a[mt][2], a[mt][3], addr);
                }
#pragma unroll
                for (int nb = 0; nb < 4; nb++) {
                    uint32_t r0, r1, r2, r3;
                    uint32_t addr = sB[pb[p]] +
                        (uint32_t)((wn * 64 + nb * 16 + lrow) * 80 + ks * 32 + lcol);
                    LDSM_X4(r0, r1, r2, r3, addr);
                    b[2 * nb][0] = r0; b[2 * nb][1] = r2;
                    b[2 * nb + 1][0] = r1; b[2 * nb + 1][1] = r3;
                }
#pragma unroll
                for (int mt = 0; mt < 2; mt++)
#pragma unroll
                    for (int nt = 0; nt < 8; nt++)
                        MMA16816(acc[mt][nt], a[mt], b[nt]);
            }
        }
        __syncthreads();
        if (c + 2 < NC) {
            load_chunk_mma(base, Ahi, Alo, Bhi, Blo, m0, n0, (c + 2) * KC, K, tid);
        }
        CP_COMMIT();
    }

    const int grow = lane >> 2;
    const int gcol = (lane & 3) * 2;
#pragma unroll
    for (int mt = 0; mt < 2; mt++) {
        int row = m0 + wm * 32 + mt * 16 + grow;
#pragma unroll
        for (int nt = 0; nt < 8; nt++) {
            int col = n0 + wn * 64 + nt * 8 + gcol;
            float* c0 = C + (size_t)row * N + col;
            float* c1 = C + (size_t)(row + 8) * N + col;
            c0[0] = acc[mt][nt][0]; c0[1] = acc[mt][nt][1];
            c1[0] = acc[mt][nt][2]; c1[1] = acc[mt][nt][3];
        }
    }
}

// ================= conversion kernels =================
__global__ __launch_bounds__(256)
void conv_split(const float* __restrict__ A, __nv_bfloat16* __restrict__ hi,
                __nv_bfloat16* __restrict__ lo, int n4)
{
    int i = blockIdx.x * blockDim.x + threadIdx.x;
    if (i >= n4) return;
    float4 v = ((const float4*)A)[i];
    __nv_bfloat16 h[4], l[4];
    float vv[4] = {v.x, v.y, v.z, v.w};
#pragma unroll
    for (int j = 0; j < 4; j++) {
        h[j] = __float2bfloat16(vv[j]);
        l[j] = __float2bfloat16(vv[j] - __bfloat162float(h[j]));
    }
    ((uint2*)hi)[i] = *(uint2*)h;
    ((uint2*)lo)[i] = *(uint2*)l;
}

__global__ __launch_bounds__(256)
void conv_w_t(const float* __restrict__ W, __nv_bfloat16* __restrict__ hi,
              __nv_bfloat16* __restrict__ lo, int K, int N)
{
    __shared__ float t[32][33];
    const int tx = threadIdx.x & 31;
    const int ty = threadIdx.x >> 5;
    const int n0 = blockIdx.x * 32;
    const int k0 = blockIdx.y * 32;
#pragma unroll
    for (int j = 0; j < 4; j++)
        t[ty + j * 8][tx] = W[(size_t)(k0 + ty + j * 8) * N + n0 + tx];
    __syncthreads();
#pragma unroll
    for (int j = 0; j < 4; j++) {
        int r = ty + j * 8;
        float v = t[tx][r];
        __nv_bfloat16 h = __float2bfloat16(v);
        __nv_bfloat16 l = __float2bfloat16(v - __bfloat162float(h));
        size_t o = (size_t)(n0 + r) * K + k0 + tx;
        hi[o] = h;
        lo[o] = l;
    }
}

// ---------------- RoPE + scatter + bf16 hi/lo split ----------------
// Q gets scale log2e/sqrt(HD) folded in (softmax later uses raw ex2).
#define QSCALE 0.1275174329213838f

__global__ __launch_bounds__(256)
void rope_bf16(const float* __restrict__ qkv,
               const float* __restrict__ sinp, const float* __restrict__ cosp,
               __nv_bfloat16* __restrict__ Qh, __nv_bfloat16* __restrict__ Ql,
               __nv_bfloat16* __restrict__ Kh, __nv_bfloat16* __restrict__ Kl,
               __nv_bfloat16* __restrict__ Vh, __nv_bfloat16* __restrict__ Vl)
{
    int idx = blockIdx.x * blockDim.x + threadIdx.x;   // B*S*H*64
    int hd = idx & 63;
    int h  = (idx >> 6) & 15;
    int s  = (idx >> 10) & 2047;
    int b  = idx >> 21;

    const float* row = qkv + ((size_t)b * S_ + s) * N3_ + h * HD_;
    float s1 = sinp[s * HD_ + hd],      c1 = cosp[s * HD_ + hd];
    float s2 = sinp[s * HD_ + hd + 64], c2 = cosp[s * HD_ + hd + 64];
    size_t ob = ((size_t)(b * H_ + h) * S_ + s) * HD_ + hd;
    {
        float x1 = row[hd], x2 = row[hd + 64];
        float q1 = (x1 * c1 - x2 * s1) * QSCALE;
        float q2 = (x2 * c2 + x1 * s2) * QSCALE;
        __nv_bfloat16 h1 = __float2bfloat16(q1), h2 = __float2bfloat16(q2);
        Qh[ob]      = h1; Ql[ob]      = __float2bfloat16(q1 - __bfloat162float(h1));
        Qh[ob + 64] = h2; Ql[ob + 64] = __float2bfloat16(q2 - __bfloat162float(h2));
    }
    {
        float x1 = row[D_ + hd], x2 = row[D_ + hd + 64];
        float k1 = x1 * c1 - x2 * s1;
        float k2 = x2 * c2 + x1 * s2;
        __nv_bfloat16 h1 = __float2bfloat16(k1), h2 = __float2bfloat16(k2);
        Kh[ob]      = h1; Kl[ob]      = __float2bfloat16(k1 - __bfloat162float(h1));
        Kh[ob + 64] = h2; Kl[ob + 64] = __float2bfloat16(k2 - __bfloat162float(h2));
    }
    {
        float v1 = row[2 * D_ + hd], v2 = row[2 * D_ + hd + 64];
        __nv_bfloat16 h1 = __float2bfloat16(v1), h2 = __float2bfloat16(v2);
        Vh[ob]      = h1; Vl[ob]      = __float2bfloat16(v1 - __bfloat162float(h1));
        Vh[ob + 64] = h2; Vl[ob + 64] = __float2bfloat16(v2 - __bfloat162float(h2));
    }
}

// ---------------- HMMA flash attention: BM=128, BN=64, HD=128 ----------------
// smem tiles: K hi/lo and V hi/lo, each [64 rows][128 bf16], stride 272 B.
#define AT_STRIDE 272
#define KT_B (64 * AT_STRIDE)         // 17408
#define KHI_OFF 0
#define KLO_OFF KT_B
#define VHI_OFF (2 * KT_B)
#define VLO_OFF (3 * KT_B)
#define STAGE_AT (4 * KT_B)           // 69632
#define ATTN_SMEM (2 * STAGE_AT)      // 139264

__device__ __forceinline__ void load_kv_tile(
    uint32_t base,
    const __nv_bfloat16* Kh, const __nv_bfloat16* Kl,
    const __nv_bfloat16* Vh, const __nv_bfloat16* Vl,
    int bh, int kt, int tid)
{
    size_t gb = ((size_t)bh * S_ + (size_t)kt * 64) * HD_;
    for (int i = tid; i < 1024; i += 256) {
        int r = i >> 4, g = i & 15;
        uint32_t so = (uint32_t)(r * AT_STRIDE + g * 16);
        size_t go = gb + (size_t)r * HD_ + g * 8;
        CP_ASYNC16(base + KHI_OFF + so, Kh + go);
        CP_ASYNC16(base + KLO_OFF + so, Kl + go);
        CP_ASYNC16(base + VHI_OFF + so, Vh + go);
        CP_ASYNC16(base + VLO_OFF + so, Vl + go);
    }
}

__global__ __launch_bounds__(256, 1)
void attn_mma(const __nv_bfloat16* __restrict__ Qh, const __nv_bfloat16* __restrict__ Ql,
              const __nv_bfloat16* __restrict__ Kh, const __nv_bfloat16* __restrict__ Kl,
              const __nv_bfloat16* __restrict__ Vh, const __nv_bfloat16* __restrict__ Vl,
              float* __restrict__ O)
{
    extern __shared__ char sm[];
    const uint32_t smb = smem_u32(sm);
    const int tid  = threadIdx.x;
    const int wid  = tid >> 5;
    const int lane = tid & 31;
    const int grow = lane >> 2;
    const int gcol2 = (lane & 3) * 2;
    const int bh = blockIdx.y;
    const int iq = gridDim.x - 1 - blockIdx.x;      // heavy tiles first
    const int row0 = iq * 128 + wid * 16;

    // ---- load Q fragments (hi/lo) directly from global ----
    uint32_t qh[8][4], ql[8][4];
    {
        const __nv_bfloat16* qb = Qh + ((size_t)bh * S_ + row0) * HD_;
        const __nv_bfloat16* qb2 = Ql + ((size_t)bh * S_ + row0) * HD_;
#pragma unroll
        for (int j = 0; j < 8; j++) {
            int c0 = j * 16 + gcol2;
            qh[j][0] = *(const uint32_t*)(qb + (size_t)grow * HD_ + c0);
            qh[j][1] = *(const uint32_t*)(qb + (size_t)(grow + 8) * HD_ + c0);
            qh[j][2] = *(const uint32_t*)(qb + (size_t)grow * HD_ + c0 + 8);
            qh[j][3] = *(const uint32_t*)(qb + (size_t)(grow + 8) * HD_ + c0 + 8);
            ql[j][0] = *(const uint32_t*)(qb2 + (size_t)grow * HD_ + c0);
            ql[j][1] = *(const uint32_t*)(qb2 + (size_t)(grow + 8) * HD_ + c0);
            ql[j][2] = *(const uint32_t*)(qb2 + (size_t)grow * HD_ + c0 + 8);
            ql[j][3] = *(const uint32_t*)(qb2 + (size_t)(grow + 8) * HD_ + c0 + 8);
        }
    }

    float o[16][4];
#pragma unroll
    for (int i = 0; i < 16; i++)
#pragma unroll
        for (int j = 0; j < 4; j++) o[i][j] = 0.f;
    float m0 = -1e30f, m1 = -1e30f, l0 = 0.f, l1 = 0.f;

    const int ktmax = 2 * iq + 1;
    const uint32_t stg0 = smb, stg1 = smb + STAGE_AT;

    load_kv_tile(stg0, Kh, Kl, Vh, Vl, bh, 0, tid);
    CP_COMMIT();
    if (ktmax >= 1) load_kv_tile(stg1, Kh, Kl, Vh, Vl, bh, 1, tid);
    CP_COMMIT();

    const int lrow = lane & 15;
    const int lcol = (lane >> 4) * 16;

    for (int kt = 0; kt <= ktmax; kt++) {
        CP_WAIT1();
        __syncthreads();
        const uint32_t stg = (kt & 1) ? stg1 : stg0;
        const bool active = (kt * 64 <= row0 + 15);

        if (active) {
            // ---- S = Q K^T : 3 passes ----
            float s[8][4];
#pragma unroll
            for (int i = 0; i < 8; i++)
#pragma unroll
                for (int j = 0; j < 4; j++) s[i][j] = 0.f;

#pragma unroll
            for (int ks = 0; ks < 8; ks++) {
                uint32_t b[8][2];
#pragma unroll
                for (int nb = 0; nb < 4; nb++) {
                    uint32_t r0, r1, r2, r3;
                    uint32_t addr = stg + KHI_OFF +
                        (uint32_t)((nb * 16 + lrow) * AT_STRIDE + ks * 32 + lcol);
                    LDSM_X4(r0, r1, r2, r3, addr);
                    b[2 * nb][0] = r0; b[2 * nb][1] = r2;
                    b[2 * nb + 1][0] = r1; b[2 * nb + 1][1] = r3;
                }
#pragma unroll
                for (int nt = 0; nt < 8; nt++) MMA16816(s[nt], qh[ks], b[nt]);
#pragma unroll
                for (int nt = 0; nt < 8; nt++) MMA16816(s[nt], ql[ks], b[nt]);
            }
#pragma unroll
            for (int ks = 0; ks < 8; ks++) {
                uint32_t b[8][2];
#pragma unroll
                for (int nb = 0; nb < 4; nb++) {
                    uint32_t r0, r1, r2, r3;
                    uint32_t addr = stg + KLO_OFF +
                        (uint32_t)((nb * 16 + lrow) * AT_STRIDE + ks * 32 + lcol);
                    LDSM_X4(r0, r1, r2, r3, addr);
                    b[2 * nb][0] = r0; b[2 * nb][1] = r2;
                    b[2 * nb + 1][0] = r1; b[2 * nb + 1][1] = r3;
                }
#pragma unroll
                for (int nt = 0; nt < 8; nt++) MMA16816(s[nt], qh[ks], b[nt]);
            }

            // ---- causal mask ----
            if (kt * 64 + 63 > row0) {
                const int kb = kt * 64;
#pragma unroll
                for (int nt = 0; nt < 8; nt++) {
#pragma unroll
                    for (int e = 0; e < 4; e++) {
                        int col = kb + nt * 8 + gcol2 + (e & 1);
                        int row = row0 + grow + ((e >> 1) << 3);
                        if (col > row) s[nt][e] = -1e30f;
                    }
                }
            }

            // ---- online softmax (log2 domain, scale folded into Q) ----
            float ml0 = -1e30f, ml1 = -1e30f;
#pragma unroll
            for (int nt = 0; nt < 8; nt++) {
                ml0 = fmaxf(ml0, fmaxf(s[nt][0], s[nt][1]));
                ml1 = fmaxf(ml1, fmaxf(s[nt][2], s[nt][3]));
            }
#pragma unroll
            for (int d = 1; d < 4; d <<= 1) {
                ml0 = fmaxf(ml0, __shfl_xor_sync(0xFFFFFFFFu, ml0, d));
                ml1 = fmaxf(ml1, __shfl_xor_sync(0xFFFFFFFFu, ml1, d));
            }
            float mn0 = fmaxf(m0, ml0), mn1 = fmaxf(m1, ml1);
            float sc0 = ex2f(m0 - mn0), sc1 = ex2f(m1 - mn1);
            float sum0 = 0.f, sum1 = 0.f;
#pragma unroll
            for (int nt = 0; nt < 8; nt++) {
                s[nt][0] = ex2f(s[nt][0] - mn0);
                s[nt][1] = ex2f(s[nt][1] - mn0);
                s[nt][2] = ex2f(s[nt][2] - mn1);
                s[nt][3] = ex2f(s[nt][3] - mn1);
                sum0 += s[nt][0] + s[nt][1];
                sum1 += s[nt][2] + s[nt][3];
            }
#pragma unroll
            for (int d = 1; d < 4; d <<= 1) {
                sum0 += __shfl_xor_sync(0xFFFFFFFFu, sum0, d);
                sum1 += __shfl_xor_sync(0xFFFFFFFFu, sum1, d);
            }
            l0 = l0 * sc0 + sum0;
            l1 = l1 * sc1 + sum1;
            m0 = mn0; m1 = mn1;
#pragma unroll
            for (int nt = 0; nt < 16; nt++) {
                o[nt][0] *= sc0; o[nt][1] *= sc0;
                o[nt][2] *= sc1; o[nt][3] *= sc1;
            }

            // ---- pack P into A-fragments (hi/lo) ----
            uint32_t pah[4][4], pal[4][4];
#pragma unroll
            for (int j = 0; j < 4; j++) {
                float p[8] = { s[2*j][0], s[2*j][1], s[2*j][2], s[2*j][3],
                               s[2*j+1][0], s[2*j+1][1], s[2*j+1][2], s[2*j+1][3] };
                float ph[8], pl[8];
#pragma unroll
                for (int e = 0; e < 8; e++) {
                    __nv_bfloat16 hb = __float2bfloat16(p[e]);
                    ph[e] = __bfloat162float(hb);
                    pl[e] = p[e] - ph[e];
                }
                pah[j][0] = pack_bf16(ph[0], ph[1]);
                pah[j][1] = pack_bf16(ph[2], ph[3]);
                pah[j][2] = pack_bf16(ph[4], ph[5]);
                pah[j][3] = pack_bf16(ph[6], ph[7]);
                pal[j][0] = pack_bf16(pl[0], pl[1]);
                pal[j][1] = pack_bf16(pl[2], pl[3]);
                pal[j][2] = pack_bf16(pl[4], pl[5]);
                pal[j][3] = pack_bf16(pl[6], pl[7]);
            }

            // ---- O += P V : 3 passes ----
#pragma unroll
            for (int ks4 = 0; ks4 < 4; ks4++) {
#pragma unroll
                for (int np = 0; np < 8; np++) {
                    uint32_t r0, r1, r2, r3;
                    uint32_t addr = stg + VHI_OFF +
                        (uint32_t)((ks4 * 16 + lrow) * AT_STRIDE + np * 32 + lcol);
                    LDSM_X4_T(r0, r1, r2, r3, addr);
                    uint32_t b0[2] = { r0, r1 }, b1[2] = { r2, r3 };
                    MMA16816(o[2 * np],     pah[ks4], b0);
                    MMA16816(o[2 * np + 1], pah[ks4], b1);
                    MMA16816(o[2 * np],     pal[ks4], b0);
                    MMA16816(o[2 * np + 1], pal[ks4], b1);
                    uint32_t addr2 = stg + VLO_OFF +
                        (uint32_t)((ks4 * 16 + lrow) * AT_STRIDE + np * 32 + lcol);
                    LDSM_X4_T(r0, r1, r2, r3, addr2);
                    uint32_t c0[2] = { r0, r1 }, c1[2] = { r2, r3 };
                    MMA16816(o[2 * np],     pah[ks4], c0);
                    MMA16816(o[2 * np + 1], pah[ks4], c1);
                }
            }
        }

        __syncthreads();
        if (kt + 2 <= ktmax)
            load_kv_tile((kt & 1) ? stg1 : stg0, Kh, Kl, Vh, Vl, bh, kt + 2, tid);
        CP_COMMIT();
    }

    // ---- epilogue ----
    const int b = bh >> 4, h = bh & 15;
    float inv0 = 1.f / l0, inv1 = 1.f / l1;
#pragma unroll
    for (int nt = 0; nt < 16; nt++) {
        int col = h * HD_ + nt * 8 + gcol2;
        float* p0 = O + ((size_t)(b * S_ + row0 + grow)) * D_ + col;
        float* p1 = O + ((size_t)(b * S_ + row0 + grow + 8)) * D_ + col;
        p0[0] = o[nt][0] * inv0; p0[1] = o[nt][1] * inv0;
        p1[0] = o[nt][2] * inv1; p1[1] = o[nt][3] * inv1;
    }
}

// ---------------- launch ----------------
extern "C" void kernel_launch(void* const* d_in, const int* in_sizes, int n_in,
                              void* d_out, int out_size)
{
    const float* x     = (const float*)d_in[0];
    // d_in[1] = mask (causal tril, handled analytically)
    const float* sinp  = (const float*)d_in[2];
    const float* cosp  = (const float*)d_in[3];
    const float* Wqkv  = (const float*)d_in[4];
    const float* Wproj = (const float*)d_in[5];
    float* out = (float*)d_out;

    float *qkv, *o;
    __nv_bfloat16 *ahi, *alo, *bhi, *blo, *qh, *ql, *kh, *kl, *vh, *vl;
    cudaGetSymbolAddress((void**)&qkv, g_qkv);
    cudaGetSymbolAddress((void**)&o,   g_o);
    cudaGetSymbolAddress((void**)&ahi, g_ahi);
    cudaGetSymbolAddress((void**)&alo, g_alo);
    cudaGetSymbolAddress((void**)&bhi, g_bhi);
    cudaGetSymbolAddress((void**)&blo, g_blo);
    cudaGetSymbolAddress((void**)&qh,  g_qhi);
    cudaGetSymbolAddress((void**)&ql,  g_qlo);
    cudaGetSymbolAddress((void**)&kh,  g_khi);
    cudaGetSymbolAddress((void**)&kl,  g_klo);
    cudaGetSymbolAddress((void**)&vh,  g_vhi);
    cudaGetSymbolAddress((void**)&vl,  g_vlo);

    cudaFuncSetAttribute(gemm_mma, cudaFuncAttributeMaxDynamicSharedMemorySize, GEMM_SMEM);
    cudaFuncSetAttribute(attn_mma, cudaFuncAttributeMaxDynamicSharedMemorySize, ATTN_SMEM);

    // 1) convert x and Wqkv
    conv_split<<<(M_ * K_ / 4 + 255) / 256, 256>>>(x, ahi, alo, M_ * K_ / 4);
    conv_w_t<<<dim3(N3_ / 32, K_ / 32), 256>>>(Wqkv, bhi, blo, K_, N3_);

    // 2) QKV projection (tensor cores)
    gemm_mma<<<dim3(N3_ / 128, M_ / 128), 256, GEMM_SMEM>>>(ahi, alo, bhi, blo, qkv, N3_, K_);

    // 3) RoPE + scatter + bf16 hi/lo split
    rope_bf16<<<B_ * S_ * H_ * 64 / 256, 256>>>(qkv, sinp, cosp, qh, ql, kh, kl, vh, vl);

    // 4) causal flash attention (tensor cores)
    attn_mma<<<dim3(S_ / 128, B_ * H_), 256, ATTN_SMEM>>>(qh, ql, kh, kl, vh, vl, o);

    // 5) output projection (tensor cores)
    conv_split<<<(M_ * K_ / 4 + 255) / 256, 256>>>(o, ahi, alo, M_ * K_ / 4);
    conv_w_t<<<dim3(D_ / 32, K_ / 32), 256>>>(Wproj, bhi, blo, K_, D_);
    gemm_mma<<<dim3(D_ / 128, M_ / 128), 256, GEMM_SMEM>>>(ahi, alo, bhi, blo, out, D_, K_);
}

// round 5
// speedup vs baseline: 6.3928x; 2.5763x over previous
#include <cuda_runtime.h>
#include <cuda_fp16.h>
#include <math.h>
#include <stdint.h>

#define B_  2
#define S_  2048
#define D_  2048
#define H_  16
#define HD_ 128
#define M_  (B_*S_)          // 4096
#define N3_ (3*D_)           // 6144
#define K_  D_               // 2048

// ---------------- scratch (device globals; no allocs allowed) ----------------
__device__ float  g_qkv[(size_t)M_ * N3_];           // qkv projection output (fp32)
__device__ __half g_a16[(size_t)M_ * K_];            // GEMM A fp16 (x, then attn out)
__device__ __half g_b16[(size_t)N3_ * K_];           // GEMM B fp16, [N,K]
__device__ __half g_q16[(size_t)(B_*H_) * S_ * HD_];
__device__ __half g_k16[(size_t)(B_*H_) * S_ * HD_];
__device__ __half g_v16[(size_t)(B_*H_) * S_ * HD_];

// ================= helpers =================
__device__ __forceinline__ uint32_t smem_u32(const void* p) {
    uint32_t a;
    asm("{ .reg .u64 t; cvta.to.shared.u64 t, %1; cvt.u32.u64 %0, t; }" : "=r"(a) : "l"(p));
    return a;
}
#define CP_ASYNC16(sm_addr, gptr) \
    asm volatile("cp.async.cg.shared.global [%0], [%1], 16;" :: "r"(sm_addr), "l"(gptr))
#define CP_COMMIT() asm volatile("cp.async.commit_group;" ::: "memory")
#define CP_WAIT1()  asm volatile("cp.async.wait_group 1;" ::: "memory")

#define LDSM_X4(r0, r1, r2, r3, addr) \
    asm volatile("ldmatrix.sync.aligned.m8n8.x4.shared.b16 {%0,%1,%2,%3}, [%4];" \
        : "=r"(r0), "=r"(r1), "=r"(r2), "=r"(r3) : "r"(addr))
#define LDSM_X4_T(r0, r1, r2, r3, addr) \
    asm volatile("ldmatrix.sync.aligned.m8n8.x4.trans.shared.b16 {%0,%1,%2,%3}, [%4];" \
        : "=r"(r0), "=r"(r1), "=r"(r2), "=r"(r3) : "r"(addr))

#define MMAH(d, a, b) \
    asm volatile("mma.sync.aligned.m16n8k16.row.col.f32.f16.f16.f32 " \
        "{%0,%1,%2,%3}, {%4,%5,%6,%7}, {%8,%9}, {%0,%1,%2,%3};" \
        : "+f"((d)[0]), "+f"((d)[1]), "+f"((d)[2]), "+f"((d)[3]) \
        : "r"((a)[0]), "r"((a)[1]), "r"((a)[2]), "r"((a)[3]), "r"((b)[0]), "r"((b)[1]))

__device__ __forceinline__ float ex2f(float x) {
    float y;
    asm("ex2.approx.f32 %0, %1;" : "=f"(y) : "f"(x));
    return y;
}
__device__ __forceinline__ uint32_t pack_h2(float a, float b) {
    __half2 t = __floats2half2_rn(a, b);
    return *(uint32_t*)&t;
}

// ================= fp16 HMMA GEMM: C[M,N] = A[M,K] @ B[N,K]^T =================
// CTA tile 128x256, 512 threads (16 warps: 4M x 4N), warp tile 32x64, KC=64.
#define KC 64
#define GA_STRIDE 144                  // 128 B data + 16 B pad (conflict-free)
#define GA_B (128 * GA_STRIDE)         // 18432
#define GB_B (256 * GA_STRIDE)         // 36864
#define GSTAGE_B (GA_B + GB_B)         // 55296
#define GEMM_SMEM (2 * GSTAGE_B)       // 110592

__device__ __forceinline__ void g_load_chunk(
    uint32_t base, const __half* A, const __half* Bt,
    int m0, int n0, int k0, int K, int tid)
{
#pragma unroll
    for (int i = tid; i < 1024; i += 512) {          // A: 128 rows x 8 granules
        int r = i >> 3, g = i & 7;
        CP_ASYNC16(base + (uint32_t)(r * GA_STRIDE + g * 16),
                   A + (size_t)(m0 + r) * K + k0 + g * 8);
    }
#pragma unroll
    for (int i = tid; i < 2048; i += 512) {          // B: 256 rows x 8 granules
        int r = i >> 3, g = i & 7;
        CP_ASYNC16(base + GA_B + (uint32_t)(r * GA_STRIDE + g * 16),
                   Bt + (size_t)(n0 + r) * K + k0 + g * 8);
    }
}

__global__ __launch_bounds__(512)
void gemm_h(const __half* __restrict__ A, const __half* __restrict__ Bt,
            float* __restrict__ C, int N, int K)
{
    extern __shared__ char sm[];
    const uint32_t smb = smem_u32(sm);
    const int tid  = threadIdx.x;
    const int wid  = tid >> 5;
    const int lane = tid & 31;
    const int wm = wid & 3;            // 4 along M
    const int wn = wid >> 2;           // 4 along N
    const int m0 = blockIdx.y * 128;
    const int n0 = blockIdx.x * 256;

    const uint32_t stg0 = smb, stg1 = smb + GSTAGE_B;

    float acc[2][8][4];
#pragma unroll
    for (int i = 0; i < 2; i++)
#pragma unroll
        for (int j = 0; j < 8; j++)
#pragma unroll
            for (int t = 0; t < 4; t++) acc[i][j][t] = 0.f;

    g_load_chunk(stg0, A, Bt, m0, n0, 0, K, tid);
    CP_COMMIT();
    g_load_chunk(stg1, A, Bt, m0, n0, KC, K, tid);
    CP_COMMIT();

    const int NC = K / KC;             // 32
    const int lrow = lane & 15;
    const int lcol = (lane >> 4) * 16;

    for (int c = 0; c < NC; c++) {
        const uint32_t base = (c & 1) ? stg1 : stg0;
        CP_WAIT1();
        __syncthreads();

#pragma unroll
        for (int ks = 0; ks < 4; ks++) {
            uint32_t a[2][4], b[8][2];
#pragma unroll
            for (int mt = 0; mt < 2; mt++) {
                uint32_t addr = base +
                    (uint32_t)((wm * 32 + mt * 16 + lrow) * GA_STRIDE + ks * 32 + lcol);
                LDSM_X4(a[mt][0], a[mt][1], a[mt][2], a[mt][3], addr);
            }
#pragma unroll
            for (int nb = 0; nb < 4; nb++) {
                uint32_t r0, r1, r2, r3;
                uint32_t addr = base + GA_B +
                    (uint32_t)((wn * 64 + nb * 16 + lrow) * GA_STRIDE + ks * 32 + lcol);
                LDSM_X4(r0, r1, r2, r3, addr);
                b[2 * nb][0] = r0; b[2 * nb][1] = r2;
                b[2 * nb + 1][0] = r1; b[2 * nb + 1][1] = r3;
            }
#pragma unroll
            for (int mt = 0; mt < 2; mt++)
#pragma unroll
                for (int nt = 0; nt < 8; nt++)
                    MMAH(acc[mt][nt], a[mt], b[nt]);
        }
        __syncthreads();
        if (c + 2 < NC)
            g_load_chunk(base, A, Bt, m0, n0, (c + 2) * KC, K, tid);
        CP_COMMIT();
    }

    const int grow = lane >> 2;
    const int gcol = (lane & 3) * 2;
#pragma unroll
    for (int mt = 0; mt < 2; mt++) {
        int row = m0 + wm * 32 + mt * 16 + grow;
#pragma unroll
        for (int nt = 0; nt < 8; nt++) {
            int col = n0 + wn * 64 + nt * 8 + gcol;
            float* c0 = C + (size_t)row * N + col;
            float* c1 = C + (size_t)(row + 8) * N + col;
            c0[0] = acc[mt][nt][0]; c0[1] = acc[mt][nt][1];
            c1[0] = acc[mt][nt][2]; c1[1] = acc[mt][nt][3];
        }
    }
}

// ================= conversion kernels =================
__global__ __launch_bounds__(256)
void conv16(const float* __restrict__ A, __half* __restrict__ out, int n4)
{
    int i = blockIdx.x * blockDim.x + threadIdx.x;
    if (i >= n4) return;
    float4 v = ((const float4*)A)[i];
    uint2 r;
    r.x = pack_h2(v.x, v.y);
    r.y = pack_h2(v.z, v.w);
    ((uint2*)out)[i] = r;
}

// W[K,N] fp32 -> Bt[N,K] fp16 transpose, 32x32 tiles
__global__ __launch_bounds__(256)
void conv_w_t16(const float* __restrict__ W, __half* __restrict__ out, int K, int N)
{
    __shared__ float t[32][33];
    const int tx = threadIdx.x & 31;
    const int ty = threadIdx.x >> 5;
    const int n0 = blockIdx.x * 32;
    const int k0 = blockIdx.y * 32;
#pragma unroll
    for (int j = 0; j < 4; j++)
        t[ty + j * 8][tx] = W[(size_t)(k0 + ty + j * 8) * N + n0 + tx];
    __syncthreads();
#pragma unroll
    for (int j = 0; j < 4; j++) {
        int r = ty + j * 8;
        out[(size_t)(n0 + r) * K + k0 + tx] = __float2half(t[tx][r]);
    }
}

// ---------------- RoPE + scatter + fp16 ----------------
#define QSCALE 0.1275174329213838f    // log2e / sqrt(128)

__global__ __launch_bounds__(256)
void rope_h(const float* __restrict__ qkv,
            const float* __restrict__ sinp, const float* __restrict__ cosp,
            __half* __restrict__ Q, __half* __restrict__ K, __half* __restrict__ V)
{
    int idx = blockIdx.x * blockDim.x + threadIdx.x;   // B*S*H*64
    int hd = idx & 63;
    int h  = (idx >> 6) & 15;
    int s  = (idx >> 10) & 2047;
    int b  = idx >> 21;

    const float* row = qkv + ((size_t)b * S_ + s) * N3_ + h * HD_;
    float s1 = sinp[s * HD_ + hd],      c1 = cosp[s * HD_ + hd];
    float s2 = sinp[s * HD_ + hd + 64], c2 = cosp[s * HD_ + hd + 64];
    size_t ob = ((size_t)(b * H_ + h) * S_ + s) * HD_ + hd;
    {
        float x1 = row[hd], x2 = row[hd + 64];
        Q[ob]      = __float2half((x1 * c1 - x2 * s1) * QSCALE);
        Q[ob + 64] = __float2half((x2 * c2 + x1 * s2) * QSCALE);
    }
    {
        float x1 = row[D_ + hd], x2 = row[D_ + hd + 64];
        K[ob]      = __float2half(x1 * c1 - x2 * s1);
        K[ob + 64] = __float2half(x2 * c2 + x1 * s2);
    }
    V[ob]      = __float2half(row[2 * D_ + hd]);
    V[ob + 64] = __float2half(row[2 * D_ + hd + 64]);
}

// ---------------- fp16 HMMA flash attention: BM=128, BN=64, HD=128 ----------------
#define AT_STRIDE 272                 // 256 B data + 16 B pad
#define KT_B (64 * AT_STRIDE)         // 17408
#define V_OFF KT_B
#define STAGE_AT (2 * KT_B)           // 34816
#define ATTN_SMEM (2 * STAGE_AT)      // 69632

__device__ __forceinline__ void load_kv_tile(
    uint32_t base, const __half* Kp, const __half* Vp, int bh, int kt, int tid)
{
    size_t gb = ((size_t)bh * S_ + (size_t)kt * 64) * HD_;
#pragma unroll
    for (int i = tid; i < 1024; i += 256) {
        int r = i >> 4, g = i & 15;
        uint32_t so = (uint32_t)(r * AT_STRIDE + g * 16);
        size_t go = gb + (size_t)r * HD_ + g * 8;
        CP_ASYNC16(base + so,        Kp + go);
        CP_ASYNC16(base + V_OFF + so, Vp + go);
    }
}

__global__ __launch_bounds__(256)
void attn_h(const __half* __restrict__ Qp, const __half* __restrict__ Kp,
            const __half* __restrict__ Vp, __half* __restrict__ Oa)
{
    extern __shared__ char sm[];
    const uint32_t smb = smem_u32(sm);
    const int tid  = threadIdx.x;
    const int wid  = tid >> 5;
    const int lane = tid & 31;
    const int grow = lane >> 2;
    const int gcol2 = (lane & 3) * 2;
    const int bh = blockIdx.y;
    const int iq = gridDim.x - 1 - blockIdx.x;      // heavy tiles first
    const int row0 = iq * 128 + wid * 16;

    // Q fragments straight from global
    uint32_t q[8][4];
    {
        const __half* qb = Qp + ((size_t)bh * S_ + row0) * HD_;
#pragma unroll
        for (int j = 0; j < 8; j++) {
            int c0 = j * 16 + gcol2;
            q[j][0] = *(const uint32_t*)(qb + (size_t)grow * HD_ + c0);
            q[j][1] = *(const uint32_t*)(qb + (size_t)(grow + 8) * HD_ + c0);
            q[j][2] = *(const uint32_t*)(qb + (size_t)grow * HD_ + c0 + 8);
            q[j][3] = *(const uint32_t*)(qb + (size_t)(grow + 8) * HD_ + c0 + 8);
        }
    }

    float o[16][4];
#pragma unroll
    for (int i = 0; i < 16; i++)
#pragma unroll
        for (int j = 0; j < 4; j++) o[i][j] = 0.f;
    float m0 = -1e30f, m1 = -1e30f, l0 = 0.f, l1 = 0.f;

    const int ktmax = 2 * iq + 1;
    const uint32_t stg0 = smb, stg1 = smb + STAGE_AT;

    load_kv_tile(stg0, Kp, Vp, bh, 0, tid);
    CP_COMMIT();
    if (ktmax >= 1) load_kv_tile(stg1, Kp, Vp, bh, 1, tid);
    CP_COMMIT();

    const int lrow = lane & 15;
    const int lcol = (lane >> 4) * 16;

    for (int kt = 0; kt <= ktmax; kt++) {
        CP_WAIT1();
        __syncthreads();
        const uint32_t stg = (kt & 1) ? stg1 : stg0;
        const bool active = (kt * 64 <= row0 + 15);

        if (active) {
            // ---- S = Q K^T ----
            float s[8][4];
#pragma unroll
            for (int i = 0; i < 8; i++)
#pragma unroll
                for (int j = 0; j < 4; j++) s[i][j] = 0.f;

#pragma unroll
            for (int ks = 0; ks < 8; ks++) {
                uint32_t b[8][2];
#pragma unroll
                for (int nb = 0; nb < 4; nb++) {
                    uint32_t r0, r1, r2, r3;
                    uint32_t addr = stg +
                        (uint32_t)((nb * 16 + lrow) * AT_STRIDE + ks * 32 + lcol);
                    LDSM_X4(r0, r1, r2, r3, addr);
                    b[2 * nb][0] = r0; b[2 * nb][1] = r2;
                    b[2 * nb + 1][0] = r1; b[2 * nb + 1][1] = r3;
                }
#pragma unroll
                for (int nt = 0; nt < 8; nt++) MMAH(s[nt], q[ks], b[nt]);
            }

            // ---- causal mask ----
            if (kt * 64 + 63 > row0) {
                const int kb = kt * 64;
#pragma unroll
                for (int nt = 0; nt < 8; nt++) {
#pragma unroll
                    for (int e = 0; e < 4; e++) {
                        int col = kb + nt * 8 + gcol2 + (e & 1);
                        int row = row0 + grow + ((e >> 1) << 3);
                        if (col > row) s[nt][e] = -1e30f;
                    }
                }
            }

            // ---- online softmax (log2 domain) ----
            float ml0 = -1e30f, ml1 = -1e30f;
#pragma unroll
            for (int nt = 0; nt < 8; nt++) {
                ml0 = fmaxf(ml0, fmaxf(s[nt][0], s[nt][1]));
                ml1 = fmaxf(ml1, fmaxf(s[nt][2], s[nt][3]));
            }
#pragma unroll
            for (int d = 1; d < 4; d <<= 1) {
                ml0 = fmaxf(ml0, __shfl_xor_sync(0xFFFFFFFFu, ml0, d));
                ml1 = fmaxf(ml1, __shfl_xor_sync(0xFFFFFFFFu, ml1, d));
            }
            float mn0 = fmaxf(m0, ml0), mn1 = fmaxf(m1, ml1);
            float sc0 = ex2f(m0 - mn0), sc1 = ex2f(m1 - mn1);
            float sum0 = 0.f, sum1 = 0.f;
#pragma unroll
            for (int nt = 0; nt < 8; nt++) {
                s[nt][0] = ex2f(s[nt][0] - mn0);
                s[nt][1] = ex2f(s[nt][1] - mn0);
                s[nt][2] = ex2f(s[nt][2] - mn1);
                s[nt][3] = ex2f(s[nt][3] - mn1);
                sum0 += s[nt][0] + s[nt][1];
                sum1 += s[nt][2] + s[nt][3];
            }
#pragma unroll
            for (int d = 1; d < 4; d <<= 1) {
                sum0 += __shfl_xor_sync(0xFFFFFFFFu, sum0, d);
                sum1 += __shfl_xor_sync(0xFFFFFFFFu, sum1, d);
            }
            l0 = l0 * sc0 + sum0;
            l1 = l1 * sc1 + sum1;
            m0 = mn0; m1 = mn1;
#pragma unroll
            for (int nt = 0; nt < 16; nt++) {
                o[nt][0] *= sc0; o[nt][1] *= sc0;
                o[nt][2] *= sc1; o[nt][3] *= sc1;
            }

            // ---- pack P into fp16 A-fragments ----
            uint32_t pa[4][4];
#pragma unroll
            for (int j = 0; j < 4; j++) {
                pa[j][0] = pack_h2(s[2*j][0],   s[2*j][1]);
                pa[j][1] = pack_h2(s[2*j][2],   s[2*j][3]);
                pa[j][2] = pack_h2(s[2*j+1][0], s[2*j+1][1]);
                pa[j][3] = pack_h2(s[2*j+1][2], s[2*j+1][3]);
            }

            // ---- O += P V ----
#pragma unroll
            for (int ks4 = 0; ks4 < 4; ks4++) {
#pragma unroll
                for (int np = 0; np < 8; np++) {
                    uint32_t r0, r1, r2, r3;
                    uint32_t addr = stg + V_OFF +
                        (uint32_t)((ks4 * 16 + lrow) * AT_STRIDE + np * 32 + lcol);
                    LDSM_X4_T(r0, r1, r2, r3, addr);
                    uint32_t b0[2] = { r0, r1 }, b1[2] = { r2, r3 };
                    MMAH(o[2 * np],     pa[ks4], b0);
                    MMAH(o[2 * np + 1], pa[ks4], b1);
                }
            }
        }

        __syncthreads();
        if (kt + 2 <= ktmax)
            load_kv_tile((kt & 1) ? stg1 : stg0, Kp, Vp, bh, kt + 2, tid);
        CP_COMMIT();
    }

    // ---- epilogue: write fp16 directly into proj-GEMM A buffer ----
    const int b = bh >> 4, h = bh & 15;
    float inv0 = 1.f / l0, inv1 = 1.f / l1;
#pragma unroll
    for (int nt = 0; nt < 16; nt++) {
        int col = h * HD_ + nt * 8 + gcol2;
        __half* p0 = Oa + ((size_t)(b * S_ + row0 + grow)) * D_ + col;
        __half* p1 = Oa + ((size_t)(b * S_ + row0 + grow + 8)) * D_ + col;
        *(uint32_t*)p0 = pack_h2(o[nt][0] * inv0, o[nt][1] * inv0);
        *(uint32_t*)p1 = pack_h2(o[nt][2] * inv1, o[nt][3] * inv1);
    }
}

// ---------------- launch ----------------
extern "C" void kernel_launch(void* const* d_in, const int* in_sizes, int n_in,
                              void* d_out, int out_size)
{
    const float* x     = (const float*)d_in[0];
    // d_in[1] = mask (causal tril, handled analytically)
    const float* sinp  = (const float*)d_in[2];
    const float* cosp  = (const float*)d_in[3];
    const float* Wqkv  = (const float*)d_in[4];
    const float* Wproj = (const float*)d_in[5];
    float* out = (float*)d_out;

    float* qkv;
    __half *a16, *b16, *q16, *k16, *v16;
    cudaGetSymbolAddress((void**)&qkv, g_qkv);
    cudaGetSymbolAddress((void**)&a16, g_a16);
    cudaGetSymbolAddress((void**)&b16, g_b16);
    cudaGetSymbolAddress((void**)&q16, g_q16);
    cudaGetSymbolAddress((void**)&k16, g_k16);
    cudaGetSymbolAddress((void**)&v16, g_v16);

    cudaFuncSetAttribute(gemm_h, cudaFuncAttributeMaxDynamicSharedMemorySize, GEMM_SMEM);
    cudaFuncSetAttribute(attn_h, cudaFuncAttributeMaxDynamicSharedMemorySize, ATTN_SMEM);

    // 1) convert x and Wqkv to fp16
    conv16<<<(M_ * K_ / 4 + 255) / 256, 256>>>(x, a16, M_ * K_ / 4);
    conv_w_t16<<<dim3(N3_ / 32, K_ / 32), 256>>>(Wqkv, b16, K_, N3_);

    // 2) QKV projection (tensor cores): [4096,2048] @ [2048,6144]
    gemm_h<<<dim3(N3_ / 256, M_ / 128), 512, GEMM_SMEM>>>(a16, b16, qkv, N3_, K_);

    // 3) RoPE + head-major scatter + fp16
    rope_h<<<B_ * S_ * H_ * 64 / 256, 256>>>(qkv, sinp, cosp, q16, k16, v16);

    // 4) causal flash attention (tensor cores); writes proj A operand fp16
    attn_h<<<dim3(S_ / 128, B_ * H_), 256, ATTN_SMEM>>>(q16, k16, v16, a16);

    // 5) output projection (tensor cores)
    conv_w_t16<<<dim3(D_ / 32, K_ / 32), 256>>>(Wproj, b16, K_, D_);
    gemm_h<<<dim3(D_ / 256, M_ / 128), 512, GEMM_SMEM>>>(a16, b16, out, D_, K_);
}

// round 7
// speedup vs baseline: 6.6801x; 1.0449x over previous
#include <cuda_runtime.h>
#include <cuda_fp16.h>
#include <math.h>
#include <stdint.h>

#define B_  2
#define S_  2048
#define D_  2048
#define H_  16
#define HD_ 128
#define M_  (B_*S_)          // 4096
#define N3_ (3*D_)           // 6144
#define K_  D_               // 2048

// ---------------- scratch (device globals; no allocs allowed) ----------------
__device__ float  g_qkv[(size_t)M_ * N3_];           // qkv projection output (fp32)
__device__ __half g_a16[(size_t)M_ * K_];            // GEMM A fp16 (x, then attn out)
__device__ __half g_b16[(size_t)N3_ * K_];           // GEMM B fp16, [N,K]
__device__ __half g_q16[(size_t)(B_*H_) * S_ * HD_];
__device__ __half g_k16[(size_t)(B_*H_) * S_ * HD_];
__device__ __half g_v16[(size_t)(B_*H_) * S_ * HD_];

// ================= helpers =================
__device__ __forceinline__ uint32_t smem_u32(const void* p) {
    uint32_t a;
    asm("{ .reg .u64 t; cvta.to.shared.u64 t, %1; cvt.u32.u64 %0, t; }" : "=r"(a) : "l"(p));
    return a;
}
#define CP_ASYNC16(sm_addr, gptr) \
    asm volatile("cp.async.cg.shared.global [%0], [%1], 16;" :: "r"(sm_addr), "l"(gptr))
#define CP_COMMIT() asm volatile("cp.async.commit_group;" ::: "memory")
#define CP_WAIT1()  asm volatile("cp.async.wait_group 1;" ::: "memory")

#define LDSM_X4(r0, r1, r2, r3, addr) \
    asm volatile("ldmatrix.sync.aligned.m8n8.x4.shared.b16 {%0,%1,%2,%3}, [%4];" \
        : "=r"(r0), "=r"(r1), "=r"(r2), "=r"(r3) : "r"(addr))
#define LDSM_X4_T(r0, r1, r2, r3, addr) \
    asm volatile("ldmatrix.sync.aligned.m8n8.x4.trans.shared.b16 {%0,%1,%2,%3}, [%4];" \
        : "=r"(r0), "=r"(r1), "=r"(r2), "=r"(r3) : "r"(addr))

#define MMAH(d, a, b) \
    asm volatile("mma.sync.aligned.m16n8k16.row.col.f32.f16.f16.f32 " \
        "{%0,%1,%2,%3}, {%4,%5,%6,%7}, {%8,%9}, {%0,%1,%2,%3};" \
        : "+f"((d)[0]), "+f"((d)[1]), "+f"((d)[2]), "+f"((d)[3]) \
        : "r"((a)[0]), "r"((a)[1]), "r"((a)[2]), "r"((a)[3]), "r"((b)[0]), "r"((b)[1]))

__device__ __forceinline__ float ex2f(float x) {
    float y;
    asm("ex2.approx.f32 %0, %1;" : "=f"(y) : "f"(x));
    return y;
}
__device__ __forceinline__ uint32_t pack_h2(float a, float b) {
    __half2 t = __floats2half2_rn(a, b);
    return *(uint32_t*)&t;
}

// ================= fp16 HMMA GEMM: C[M,N] = A[M,K] @ B[N,K]^T =================
// CTA tile 128x256, 512 threads (16 warps: 4M x 4N), KC=64, 3-stage ring,
// single __syncthreads per chunk.
#define KC 64
#define GA_STRIDE 144                  // 128 B data + 16 B pad (conflict-free)
#define GA_B (128 * GA_STRIDE)         // 18432
#define GB_B (256 * GA_STRIDE)         // 36864
#define GSTAGE_B (GA_B + GB_B)         // 55296
#define GEMM_NS 3
#define GEMM_SMEM (GEMM_NS * GSTAGE_B) // 165888

__device__ __forceinline__ void g_load_chunk(
    uint32_t base, const __half* A, const __half* Bt,
    int m0, int n0, int k0, int K, int tid)
{
#pragma unroll
    for (int i = tid; i < 1024; i += 512) {          // A: 128 rows x 8 granules
        int r = i >> 3, g = i & 7;
        CP_ASYNC16(base + (uint32_t)(r * GA_STRIDE + g * 16),
                   A + (size_t)(m0 + r) * K + k0 + g * 8);
    }
#pragma unroll
    for (int i = tid; i < 2048; i += 512) {          // B: 256 rows x 8 granules
        int r = i >> 3, g = i & 7;
        CP_ASYNC16(base + GA_B + (uint32_t)(r * GA_STRIDE + g * 16),
                   Bt + (size_t)(n0 + r) * K + k0 + g * 8);
    }
}

__global__ __launch_bounds__(512)
void gemm_h(const __half* __restrict__ A, const __half* __restrict__ Bt,
            float* __restrict__ C, int N, int K)
{
    extern __shared__ char sm[];
    const uint32_t smb = smem_u32(sm);
    const int tid  = threadIdx.x;
    const int wid  = tid >> 5;
    const int lane = tid & 31;
    const int wm = wid & 3;            // 4 along M
    const int wn = wid >> 2;           // 4 along N
    const int m0 = blockIdx.y * 128;
    const int n0 = blockIdx.x * 256;

    float acc[2][8][4];
#pragma unroll
    for (int i = 0; i < 2; i++)
#pragma unroll
        for (int j = 0; j < 8; j++)
#pragma unroll
            for (int t = 0; t < 4; t++) acc[i][j][t] = 0.f;

    // prologue: 2 chunks in flight
    g_load_chunk(smb,            A, Bt, m0, n0, 0,  K, tid);
    CP_COMMIT();
    g_load_chunk(smb + GSTAGE_B, A, Bt, m0, n0, KC, K, tid);
    CP_COMMIT();

    const int NC = K / KC;             // 32
    const int lrow = lane & 15;
    const int lcol = (lane >> 4) * 16;

    int stage = 0;
    for (int c = 0; c < NC; c++) {
        CP_WAIT1();                    // chunk c done (c+1 may be in flight)
        __syncthreads();               // all warps finished chunk c-1 compute

        // issue chunk c+2 into the stage chunk c-1 just vacated
        if (c + 2 < NC) {
            int ns = stage + 2; if (ns >= GEMM_NS) ns -= GEMM_NS;
            g_load_chunk(smb + (uint32_t)ns * GSTAGE_B, A, Bt, m0, n0, (c + 2) * KC, K, tid);
        }
        CP_COMMIT();

        const uint32_t base = smb + (uint32_t)stage * GSTAGE_B;
#pragma unroll
        for (int ks = 0; ks < 4; ks++) {
            uint32_t a[2][4], b[8][2];
#pragma unroll
            for (int mt = 0; mt < 2; mt++) {
                uint32_t addr = base +
                    (uint32_t)((wm * 32 + mt * 16 + lrow) * GA_STRIDE + ks * 32 + lcol);
                LDSM_X4(a[mt][0], a[mt][1], a[mt][2], a[mt][3], addr);
            }
#pragma unroll
            for (int nb = 0; nb < 4; nb++) {
                uint32_t r0, r1, r2, r3;
                uint32_t addr = base + GA_B +
                    (uint32_t)((wn * 64 + nb * 16 + lrow) * GA_STRIDE + ks * 32 + lcol);
                LDSM_X4(r0, r1, r2, r3, addr);
                b[2 * nb][0] = r0; b[2 * nb][1] = r2;
                b[2 * nb + 1][0] = r1; b[2 * nb + 1][1] = r3;
            }
#pragma unroll
            for (int mt = 0; mt < 2; mt++)
#pragma unroll
                for (int nt = 0; nt < 8; nt++)
                    MMAH(acc[mt][nt], a[mt], b[nt]);
        }
        if (++stage == GEMM_NS) stage = 0;
    }

    const int grow = lane >> 2;
    const int gcol = (lane & 3) * 2;
#pragma unroll
    for (int mt = 0; mt < 2; mt++) {
        int row = m0 + wm * 32 + mt * 16 + grow;
#pragma unroll
        for (int nt = 0; nt < 8; nt++) {
            int col = n0 + wn * 64 + nt * 8 + gcol;
            float* c0 = C + (size_t)row * N + col;
            float* c1 = C + (size_t)(row + 8) * N + col;
            c0[0] = acc[mt][nt][0]; c0[1] = acc[mt][nt][1];
            c1[0] = acc[mt][nt][2]; c1[1] = acc[mt][nt][3];
        }
    }
}

// ================= conversion kernels =================
__global__ __launch_bounds__(256)
void conv16(const float* __restrict__ A, __half* __restrict__ out, int n4)
{
    int i = blockIdx.x * blockDim.x + threadIdx.x;
    if (i >= n4) return;
    float4 v = ((const float4*)A)[i];
    uint2 r;
    r.x = pack_h2(v.x, v.y);
    r.y = pack_h2(v.z, v.w);
    ((uint2*)out)[i] = r;
}

// W[K,N] fp32 -> Bt[N,K] fp16 transpose, 32x32 tiles
__global__ __launch_bounds__(256)
void conv_w_t16(const float* __restrict__ W, __half* __restrict__ out, int K, int N)
{
    __shared__ float t[32][33];
    const int tx = threadIdx.x & 31;
    const int ty = threadIdx.x >> 5;
    const int n0 = blockIdx.x * 32;
    const int k0 = blockIdx.y * 32;
#pragma unroll
    for (int j = 0; j < 4; j++)
        t[ty + j * 8][tx] = W[(size_t)(k0 + ty + j * 8) * N + n0 + tx];
    __syncthreads();
#pragma unroll
    for (int j = 0; j < 4; j++) {
        int r = ty + j * 8;
        out[(size_t)(n0 + r) * K + k0 + tx] = __float2half(t[tx][r]);
    }
}

// ---------------- RoPE + scatter + fp16 ----------------
#define QSCALE 0.1275174329213838f    // log2e / sqrt(128)

__global__ __launch_bounds__(256)
void rope_h(const float* __restrict__ qkv,
            const float* __restrict__ sinp, const float* __restrict__ cosp,
            __half* __restrict__ Q, __half* __restrict__ K, __half* __restrict__ V)
{
    int idx = blockIdx.x * blockDim.x + threadIdx.x;   // B*S*H*64
    int hd = idx & 63;
    int h  = (idx >> 6) & 15;
    int s  = (idx >> 10) & 2047;
    int b  = idx >> 21;

    const float* row = qkv + ((size_t)b * S_ + s) * N3_ + h * HD_;
    float s1 = sinp[s * HD_ + hd],      c1 = cosp[s * HD_ + hd];
    float s2 = sinp[s * HD_ + hd + 64], c2 = cosp[s * HD_ + hd + 64];
    size_t ob = ((size_t)(b * H_ + h) * S_ + s) * HD_ + hd;
    {
        float x1 = row[hd], x2 = row[hd + 64];
        Q[ob]      = __float2half((x1 * c1 - x2 * s1) * QSCALE);
        Q[ob + 64] = __float2half((x2 * c2 + x1 * s2) * QSCALE);
    }
    {
        float x1 = row[D_ + hd], x2 = row[D_ + hd + 64];
        K[ob]      = __float2half(x1 * c1 - x2 * s1);
        K[ob + 64] = __float2half(x2 * c2 + x1 * s2);
    }
    V[ob]      = __float2half(row[2 * D_ + hd]);
    V[ob + 64] = __float2half(row[2 * D_ + hd + 64]);
}

// ---------------- fp16 HMMA flash attention: BM=128, BN=64, HD=128 ----------------
// 3-stage ring, single __syncthreads per key-tile.
#define AT_STRIDE 272                 // 256 B data + 16 B pad
#define KT_B (64 * AT_STRIDE)         // 17408
#define V_OFF KT_B
#define STAGE_AT (2 * KT_B)           // 34816
#define ATTN_NS 3
#define ATTN_SMEM (ATTN_NS * STAGE_AT)  // 104448

__device__ __forceinline__ void load_kv_tile(
    uint32_t base, const __half* Kp, const __half* Vp, int bh, int kt, int tid)
{
    size_t gb = ((size_t)bh * S_ + (size_t)kt * 64) * HD_;
#pragma unroll
    for (int i = tid; i < 1024; i += 256) {
        int r = i >> 4, g = i & 15;
        uint32_t so = (uint32_t)(r * AT_STRIDE + g * 16);
        size_t go = gb + (size_t)r * HD_ + g * 8;
        CP_ASYNC16(base + so,        Kp + go);
        CP_ASYNC16(base + V_OFF + so, Vp + go);
    }
}

__global__ __launch_bounds__(256)
void attn_h(const __half* __restrict__ Qp, const __half* __restrict__ Kp,
            const __half* __restrict__ Vp, __half* __restrict__ Oa)
{
    extern __shared__ char sm[];
    const uint32_t smb = smem_u32(sm);
    const int tid  = threadIdx.x;
    const int wid  = tid >> 5;
    const int lane = tid & 31;
    const int grow = lane >> 2;
    const int gcol2 = (lane & 3) * 2;
    const int bh = blockIdx.y;
    const int iq = gridDim.x - 1 - blockIdx.x;      // heavy tiles first
    const int row0 = iq * 128 + wid * 16;

    // Q fragments straight from global
    uint32_t q[8][4];
    {
        const __half* qb = Qp + ((size_t)bh * S_ + row0) * HD_;
#pragma unroll
        for (int j = 0; j < 8; j++) {
            int c0 = j * 16 + gcol2;
            q[j][0] = *(const uint32_t*)(qb + (size_t)grow * HD_ + c0);
            q[j][1] = *(const uint32_t*)(qb + (size_t)(grow + 8) * HD_ + c0);
            q[j][2] = *(const uint32_t*)(qb + (size_t)grow * HD_ + c0 + 8);
            q[j][3] = *(const uint32_t*)(qb + (size_t)(grow + 8) * HD_ + c0 + 8);
        }
    }

    float o[16][4];
#pragma unroll
    for (int i = 0; i < 16; i++)
#pragma unroll
        for (int j = 0; j < 4; j++) o[i][j] = 0.f;
    float m0 = -1e30f, m1 = -1e30f, l0 = 0.f, l1 = 0.f;

    const int ktmax = 2 * iq + 1;

    load_kv_tile(smb, Kp, Vp, bh, 0, tid);
    CP_COMMIT();
    if (ktmax >= 1) load_kv_tile(smb + STAGE_AT, Kp, Vp, bh, 1, tid);
    CP_COMMIT();

    const int lrow = lane & 15;
    const int lcol = (lane >> 4) * 16;

    int stage = 0;
    for (int kt = 0; kt <= ktmax; kt++) {
        CP_WAIT1();
        __syncthreads();

        // issue kt+2 into the stage kt-1 just vacated
        if (kt + 2 <= ktmax) {
            int ns = stage + 2; if (ns >= ATTN_NS) ns -= ATTN_NS;
            load_kv_tile(smb + (uint32_t)ns * STAGE_AT, Kp, Vp, bh, kt + 2, tid);
        }
        CP_COMMIT();

        const uint32_t stg = smb + (uint32_t)stage * STAGE_AT;
        const bool active = (kt * 64 <= row0 + 15);

        if (active) {
            // ---- S = Q K^T ----
            float s[8][4];
#pragma unroll
            for (int i = 0; i < 8; i++)
#pragma unroll
                for (int j = 0; j < 4; j++) s[i][j] = 0.f;

#pragma unroll
            for (int ks = 0; ks < 8; ks++) {
                uint32_t b[8][2];
#pragma unroll
                for (int nb = 0; nb < 4; nb++) {
                    uint32_t r0, r1, r2, r3;
                    uint32_t addr = stg +
                        (uint32_t)((nb * 16 + lrow) * AT_STRIDE + ks * 32 + lcol);
                    LDSM_X4(r0, r1, r2, r3, addr);
                    b[2 * nb][0] = r0; b[2 * nb][1] = r2;
                    b[2 * nb + 1][0] = r1; b[2 * nb + 1][1] = r3;
                }
#pragma unroll
                for (int nt = 0; nt < 8; nt++) MMAH(s[nt], q[ks], b[nt]);
            }

            // ---- causal mask ----
            if (kt * 64 + 63 > row0) {
                const int kb = kt * 64;
#pragma unroll
                for (int nt = 0; nt < 8; nt++) {
#pragma unroll
                    for (int e = 0; e < 4; e++) {
                        int col = kb + nt * 8 + gcol2 + (e & 1);
                        int row = row0 + grow + ((e >> 1) << 3);
                        if (col > row) s[nt][e] = -1e30f;
                    }
                }
            }

            // ---- online softmax (log2 domain) ----
            float ml0 = -1e30f, ml1 = -1e30f;
#pragma unroll
            for (int nt = 0; nt < 8; nt++) {
                ml0 = fmaxf(ml0, fmaxf(s[nt][0], s[nt][1]));
                ml1 = fmaxf(ml1, fmaxf(s[nt][2], s[nt][3]));
            }
#pragma unroll
            for (int d = 1; d < 4; d <<= 1) {
                ml0 = fmaxf(ml0, __shfl_xor_sync(0xFFFFFFFFu, ml0, d));
                ml1 = fmaxf(ml1, __shfl_xor_sync(0xFFFFFFFFu, ml1, d));
            }
            float mn0 = fmaxf(m0, ml0), mn1 = fmaxf(m1, ml1);
            float sc0 = ex2f(m0 - mn0), sc1 = ex2f(m1 - mn1);
            float sum0 = 0.f, sum1 = 0.f;
#pragma unroll
            for (int nt = 0; nt < 8; nt++) {
                s[nt][0] = ex2f(s[nt][0] - mn0);
                s[nt][1] = ex2f(s[nt][1] - mn0);
                s[nt][2] = ex2f(s[nt][2] - mn1);
                s[nt][3] = ex2f(s[nt][3] - mn1);
                sum0 += s[nt][0] + s[nt][1];
                sum1 += s[nt][2] + s[nt][3];
            }
#pragma unroll
            for (int d = 1; d < 4; d <<= 1) {
                sum0 += __shfl_xor_sync(0xFFFFFFFFu, sum0, d);
                sum1 += __shfl_xor_sync(0xFFFFFFFFu, sum1, d);
            }
            l0 = l0 * sc0 + sum0;
            l1 = l1 * sc1 + sum1;
            m0 = mn0; m1 = mn1;
#pragma unroll
            for (int nt = 0; nt < 16; nt++) {
                o[nt][0] *= sc0; o[nt][1] *= sc0;
                o[nt][2] *= sc1; o[nt][3] *= sc1;
            }

            // ---- pack P into fp16 A-fragments ----
            uint32_t pa[4][4];
#pragma unroll
            for (int j = 0; j < 4; j++) {
                pa[j][0] = pack_h2(s[2*j][0],   s[2*j][1]);
                pa[j][1] = pack_h2(s[2*j][2],   s[2*j][3]);
                pa[j][2] = pack_h2(s[2*j+1][0], s[2*j+1][1]);
                pa[j][3] = pack_h2(s[2*j+1][2], s[2*j+1][3]);
            }

            // ---- O += P V ----
#pragma unroll
            for (int ks4 = 0; ks4 < 4; ks4++) {
#pragma unroll
                for (int np = 0; np < 8; np++) {
                    uint32_t r0, r1, r2, r3;
                    uint32_t addr = stg + V_OFF +
                        (uint32_t)((ks4 * 16 + lrow) * AT_STRIDE + np * 32 + lcol);
                    LDSM_X4_T(r0, r1, r2, r3, addr);
                    uint32_t b0[2] = { r0, r1 }, b1[2] = { r2, r3 };
                    MMAH(o[2 * np],     pa[ks4], b0);
                    MMAH(o[2 * np + 1], pa[ks4], b1);
                }
            }
        }
        if (++stage == ATTN_NS) stage = 0;
    }

    // ---- epilogue: write fp16 directly into proj-GEMM A buffer ----
    const int b = bh >> 4, h = bh & 15;
    float inv0 = 1.f / l0, inv1 = 1.f / l1;
#pragma unroll
    for (int nt = 0; nt < 16; nt++) {
        int col = h * HD_ + nt * 8 + gcol2;
        __half* p0 = Oa + ((size_t)(b * S_ + row0 + grow)) * D_ + col;
        __half* p1 = Oa + ((size_t)(b * S_ + row0 + grow + 8)) * D_ + col;
        *(uint32_t*)p0 = pack_h2(o[nt][0] * inv0, o[nt][1] * inv0);
        *(uint32_t*)p1 = pack_h2(o[nt][2] * inv1, o[nt][3] * inv1);
    }
}

// ---------------- launch ----------------
extern "C" void kernel_launch(void* const* d_in, const int* in_sizes, int n_in,
                              void* d_out, int out_size)
{
    const float* x     = (const float*)d_in[0];
    // d_in[1] = mask (causal tril, handled analytically)
    const float* sinp  = (const float*)d_in[2];
    const float* cosp  = (const float*)d_in[3];
    const float* Wqkv  = (const float*)d_in[4];
    const float* Wproj = (const float*)d_in[5];
    float* out = (float*)d_out;

    float* qkv;
    __half *a16, *b16, *q16, *k16, *v16;
    cudaGetSymbolAddress((void**)&qkv, g_qkv);
    cudaGetSymbolAddress((void**)&a16, g_a16);
    cudaGetSymbolAddress((void**)&b16, g_b16);
    cudaGetSymbolAddress((void**)&q16, g_q16);
    cudaGetSymbolAddress((void**)&k16, g_k16);
    cudaGetSymbolAddress((void**)&v16, g_v16);

    cudaFuncSetAttribute(gemm_h, cudaFuncAttributeMaxDynamicSharedMemorySize, GEMM_SMEM);
    cudaFuncSetAttribute(attn_h, cudaFuncAttributeMaxDynamicSharedMemorySize, ATTN_SMEM);

    // 1) convert x and Wqkv to fp16
    conv16<<<(M_ * K_ / 4 + 255) / 256, 256>>>(x, a16, M_ * K_ / 4);
    conv_w_t16<<<dim3(N3_ / 32, K_ / 32), 256>>>(Wqkv, b16, K_, N3_);

    // 2) QKV projection (tensor cores): [4096,2048] @ [2048,6144]
    gemm_h<<<dim3(N3_ / 256, M_ / 128), 512, GEMM_SMEM>>>(a16, b16, qkv, N3_, K_);

    // 3) RoPE + head-major scatter + fp16
    rope_h<<<B_ * S_ * H_ * 64 / 256, 256>>>(qkv, sinp, cosp, q16, k16, v16);

    // 4) causal flash attention (tensor cores); writes proj A operand fp16
    attn_h<<<dim3(S_ / 128, B_ * H_), 256, ATTN_SMEM>>>(q16, k16, v16, a16);

    // 5) output projection (tensor cores)
    conv_w_t16<<<dim3(D_ / 32, K_ / 32), 256>>>(Wproj, b16, K_, D_);
    gemm_h<<<dim3(D_ / 256, M_ / 128), 512, GEMM_SMEM>>>(a16, b16, out, D_, K_);
}

// round 8
// speedup vs baseline: 6.8144x; 1.0201x over previous
#include <cuda_runtime.h>
#include <cuda_fp16.h>
#include <math.h>
#include <stdint.h>

#define B_  2
#define S_  2048
#define D_  2048
#define H_  16
#define HD_ 128
#define M_  (B_*S_)          // 4096
#define N3_ (3*D_)           // 6144
#define K_  D_               // 2048

// ---------------- scratch (device globals; no allocs allowed) ----------------
__device__ __half g_a16[(size_t)M_ * K_];            // GEMM A fp16 (x, then attn out)
__device__ __half g_b16[(size_t)N3_ * K_];           // GEMM B fp16, [N,K]
__device__ __half g_q16[(size_t)(B_*H_) * S_ * HD_];
__device__ __half g_k16[(size_t)(B_*H_) * S_ * HD_];
__device__ __half g_v16[(size_t)(B_*H_) * S_ * HD_];

// ================= helpers =================
__device__ __forceinline__ uint32_t smem_u32(const void* p) {
    uint32_t a;
    asm("{ .reg .u64 t; cvta.to.shared.u64 t, %1; cvt.u32.u64 %0, t; }" : "=r"(a) : "l"(p));
    return a;
}
#define CP_ASYNC16(sm_addr, gptr) \
    asm volatile("cp.async.cg.shared.global [%0], [%1], 16;" :: "r"(sm_addr), "l"(gptr))
#define CP_COMMIT() asm volatile("cp.async.commit_group;" ::: "memory")
#define CP_WAIT1()  asm volatile("cp.async.wait_group 1;" ::: "memory")

#define LDSM_X4(r0, r1, r2, r3, addr) \
    asm volatile("ldmatrix.sync.aligned.m8n8.x4.shared.b16 {%0,%1,%2,%3}, [%4];" \
        : "=r"(r0), "=r"(r1), "=r"(r2), "=r"(r3) : "r"(addr))
#define LDSM_X4_T(r0, r1, r2, r3, addr) \
    asm volatile("ldmatrix.sync.aligned.m8n8.x4.trans.shared.b16 {%0,%1,%2,%3}, [%4];" \
        : "=r"(r0), "=r"(r1), "=r"(r2), "=r"(r3) : "r"(addr))

#define MMAH(d, a, b) \
    asm volatile("mma.sync.aligned.m16n8k16.row.col.f32.f16.f16.f32 " \
        "{%0,%1,%2,%3}, {%4,%5,%6,%7}, {%8,%9}, {%0,%1,%2,%3};" \
        : "+f"((d)[0]), "+f"((d)[1]), "+f"((d)[2]), "+f"((d)[3]) \
        : "r"((a)[0]), "r"((a)[1]), "r"((a)[2]), "r"((a)[3]), "r"((b)[0]), "r"((b)[1]))

__device__ __forceinline__ float ex2f(float x) {
    float y;
    asm("ex2.approx.f32 %0, %1;" : "=f"(y) : "f"(x));
    return y;
}
__device__ __forceinline__ uint32_t pack_h2(float a, float b) {
    __half2 t = __floats2half2_rn(a, b);
    return *(uint32_t*)&t;
}

// ================= fp16 HMMA GEMM common =================
// CTA tile 128x256, 512 threads (16 warps: 4M x 4N), KC=64, 3-stage ring.
#define KC 64
#define GA_STRIDE 144                  // 128 B data + 16 B pad (conflict-free)
#define GA_B (128 * GA_STRIDE)         // 18432
#define GB_B (256 * GA_STRIDE)         // 36864
#define GSTAGE_B (GA_B + GB_B)         // 55296
#define GEMM_NS 3
#define GEMM_SMEM (GEMM_NS * GSTAGE_B) // 165888  (>= 128*260*4 epilogue staging)
#define CS_STRIDE 260                  // fp32 epilogue staging stride (1040 B, 16B-aligned)

__device__ __forceinline__ void g_load_chunk(
    uint32_t base, const __half* A, const __half* Bt,
    int m0, int n0, int k0, int K, int tid)
{
#pragma unroll
    for (int i = tid; i < 1024; i += 512) {          // A: 128 rows x 8 granules
        int r = i >> 3, g = i & 7;
        CP_ASYNC16(base + (uint32_t)(r * GA_STRIDE + g * 16),
                   A + (size_t)(m0 + r) * K + k0 + g * 8);
    }
#pragma unroll
    for (int i = tid; i < 2048; i += 512) {          // B: 256 rows x 8 granules
        int r = i >> 3, g = i & 7;
        CP_ASYNC16(base + GA_B + (uint32_t)(r * GA_STRIDE + g * 16),
                   Bt + (size_t)(n0 + r) * K + k0 + g * 8);
    }
}

// mainloop shared by both GEMMs; leaves accumulators in acc[2][8][4]
__device__ __forceinline__ void gemm_mainloop(
    uint32_t smb, const __half* A, const __half* Bt,
    int m0, int n0, int K, int tid, int wm, int wn, int lane,
    float acc[2][8][4])
{
#pragma unroll
    for (int i = 0; i < 2; i++)
#pragma unroll
        for (int j = 0; j < 8; j++)
#pragma unroll
            for (int t = 0; t < 4; t++) acc[i][j][t] = 0.f;

    g_load_chunk(smb,            A, Bt, m0, n0, 0,  K, tid);
    CP_COMMIT();
    g_load_chunk(smb + GSTAGE_B, A, Bt, m0, n0, KC, K, tid);
    CP_COMMIT();

    const int NC = K / KC;
    const int lrow = lane & 15;
    const int lcol = (lane >> 4) * 16;

    int stage = 0;
    for (int c = 0; c < NC; c++) {
        CP_WAIT1();
        __syncthreads();

        if (c + 2 < NC) {
            int ns = stage + 2; if (ns >= GEMM_NS) ns -= GEMM_NS;
            g_load_chunk(smb + (uint32_t)ns * GSTAGE_B, A, Bt, m0, n0, (c + 2) * KC, K, tid);
        }
        CP_COMMIT();

        const uint32_t base = smb + (uint32_t)stage * GSTAGE_B;
#pragma unroll
        for (int ks = 0; ks < 4; ks++) {
            uint32_t a[2][4], b[8][2];
#pragma unroll
            for (int mt = 0; mt < 2; mt++) {
                uint32_t addr = base +
                    (uint32_t)((wm * 32 + mt * 16 + lrow) * GA_STRIDE + ks * 32 + lcol);
                LDSM_X4(a[mt][0], a[mt][1], a[mt][2], a[mt][3], addr);
            }
#pragma unroll
            for (int nb = 0; nb < 4; nb++) {
                uint32_t r0, r1, r2, r3;
                uint32_t addr = base + GA_B +
                    (uint32_t)((wn * 64 + nb * 16 + lrow) * GA_STRIDE + ks * 32 + lcol);
                LDSM_X4(r0, r1, r2, r3, addr);
                b[2 * nb][0] = r0; b[2 * nb][1] = r2;
                b[2 * nb + 1][0] = r1; b[2 * nb + 1][1] = r3;
            }
#pragma unroll
            for (int mt = 0; mt < 2; mt++)
#pragma unroll
                for (int nt = 0; nt < 8; nt++)
                    MMAH(acc[mt][nt], a[mt], b[nt]);
        }
        if (++stage == GEMM_NS) stage = 0;
    }
}

// ---------- generic GEMM (fp32 out) for the output projection ----------
__global__ __launch_bounds__(512)
void gemm_h(const __half* __restrict__ A, const __half* __restrict__ Bt,
            float* __restrict__ C, int N, int K)
{
    extern __shared__ char sm[];
    const uint32_t smb = smem_u32(sm);
    const int tid  = threadIdx.x;
    const int wid  = tid >> 5;
    const int lane = tid & 31;
    const int wm = wid & 3;
    const int wn = wid >> 2;
    const int m0 = blockIdx.y * 128;
    const int n0 = blockIdx.x * 256;

    float acc[2][8][4];
    gemm_mainloop(smb, A, Bt, m0, n0, K, tid, wm, wn, lane, acc);

    const int grow = lane >> 2;
    const int gcol = (lane & 3) * 2;
#pragma unroll
    for (int mt = 0; mt < 2; mt++) {
        int row = m0 + wm * 32 + mt * 16 + grow;
#pragma unroll
        for (int nt = 0; nt < 8; nt++) {
            int col = n0 + wn * 64 + nt * 8 + gcol;
            float* c0 = C + (size_t)row * N + col;
            float* c1 = C + (size_t)(row + 8) * N + col;
            c0[0] = acc[mt][nt][0]; c0[1] = acc[mt][nt][1];
            c1[0] = acc[mt][nt][2]; c1[1] = acc[mt][nt][3];
        }
    }
}

// ---------- QKV GEMM with fused RoPE + fp16 scatter epilogue ----------
#define QSCALE 0.1275174329213838f    // log2e / sqrt(128)

__global__ __launch_bounds__(512)
void gemm_qkv(const __half* __restrict__ A, const __half* __restrict__ Bt,
              const float* __restrict__ sinp, const float* __restrict__ cosp,
              __half* __restrict__ Qo, __half* __restrict__ Ko, __half* __restrict__ Vo)
{
    extern __shared__ char sm[];
    const uint32_t smb = smem_u32(sm);
    const int tid  = threadIdx.x;
    const int wid  = tid >> 5;
    const int lane = tid & 31;
    const int wm = wid & 3;
    const int wn = wid >> 2;
    const int m0 = blockIdx.y * 128;
    const int n0 = blockIdx.x * 256;

    float acc[2][8][4];
    gemm_mainloop(smb, A, Bt, m0, n0, K_, tid, wm, wn, lane, acc);

    // ---- stage fp32 accs in smem (pipeline stages are retired) ----
    __syncthreads();
    float* cs = (float*)sm;
    const int grow = lane >> 2;
    const int gcol = (lane & 3) * 2;
#pragma unroll
    for (int mt = 0; mt < 2; mt++) {
        int r = wm * 32 + mt * 16 + grow;
#pragma unroll
        for (int nt = 0; nt < 8; nt++) {
            int col = wn * 64 + nt * 8 + gcol;
            cs[r * CS_STRIDE + col]       = acc[mt][nt][0];
            cs[r * CS_STRIDE + col + 1]   = acc[mt][nt][1];
            cs[(r + 8) * CS_STRIDE + col]     = acc[mt][nt][2];
            cs[(r + 8) * CS_STRIDE + col + 1] = acc[mt][nt][3];
        }
    }
    __syncthreads();

    // ---- RoPE + fp16 + head-major scatter ----
    // tile covers one of q/k/v entirely and exactly 2 heads
    const int which = n0 >> 11;            // 0=q, 1=k, 2=v
    const int h0 = (n0 & 2047) >> 7;       // first head in tile

    for (int it = tid; it < 128 * 64; it += 512) {
        int r  = it >> 6;                  // tile row 0..127
        int qd = (it & 63) << 2;           // tile col quad 0..252
        int hh = qd >> 7;                  // head-in-tile 0/1
        int hd = qd & 127;                 // headdim pos (multiple of 4)
        int m = m0 + r;
        int b = m >> 11, s = m & 2047;

        float4 v = *(float4*)&cs[r * CS_STRIDE + qd];
        float out0, out1, out2, out3;

        if (which == 2) {
            out0 = v.x; out1 = v.y; out2 = v.z; out3 = v.w;
        } else {
            float4 c4 = *(const float4*)&cosp[s * HD_ + hd];
            float4 s4 = *(const float4*)&sinp[s * HD_ + hd];
            float4 rv;
            if (hd < 64) {
                float4 t = *(float4*)&cs[r * CS_STRIDE + qd + 64];
                rv.x = -t.x; rv.y = -t.y; rv.z = -t.z; rv.w = -t.w;
            } else {
                rv = *(float4*)&cs[r * CS_STRIDE + qd - 64];
            }
            out0 = v.x * c4.x + rv.x * s4.x;
            out1 = v.y * c4.y + rv.y * s4.y;
            out2 = v.z * c4.z + rv.z * s4.z;
            out3 = v.w * c4.w + rv.w * s4.w;
            if (which == 0) {
                out0 *= QSCALE; out1 *= QSCALE; out2 *= QSCALE; out3 *= QSCALE;
            }
        }
        __half* dst = (which == 0) ? Qo : (which == 1) ? Ko : Vo;
        size_t ob = (((size_t)(b * H_ + h0 + hh)) * S_ + s) * HD_ + hd;
        uint2 pk;
        pk.x = pack_h2(out0, out1);
        pk.y = pack_h2(out2, out3);
        *(uint2*)(dst + ob) = pk;
    }
}

// ================= conversion kernels =================
__global__ __launch_bounds__(256)
void conv16(const float* __restrict__ A, __half* __restrict__ out, int n4)
{
    int i = blockIdx.x * blockDim.x + threadIdx.x;
    if (i >= n4) return;
    float4 v = ((const float4*)A)[i];
    uint2 r;
    r.x = pack_h2(v.x, v.y);
    r.y = pack_h2(v.z, v.w);
    ((uint2*)out)[i] = r;
}

// W[K,N] fp32 -> Bt[N,K] fp16 transpose, 32x32 tiles
__global__ __launch_bounds__(256)
void conv_w_t16(const float* __restrict__ W, __half* __restrict__ out, int K, int N)
{
    __shared__ float t[32][33];
    const int tx = threadIdx.x & 31;
    const int ty = threadIdx.x >> 5;
    const int n0 = blockIdx.x * 32;
    const int k0 = blockIdx.y * 32;
#pragma unroll
    for (int j = 0; j < 4; j++)
        t[ty + j * 8][tx] = W[(size_t)(k0 + ty + j * 8) * N + n0 + tx];
    __syncthreads();
#pragma unroll
    for (int j = 0; j < 4; j++) {
        int r = ty + j * 8;
        out[(size_t)(n0 + r) * K + k0 + tx] = __float2half(t[tx][r]);
    }
}

// ---------------- fp16 HMMA flash attention: BM=128, BN=64, HD=128 ----------------
#define AT_STRIDE 272                 // 256 B data + 16 B pad
#define KT_B (64 * AT_STRIDE)         // 17408
#define V_OFF KT_B
#define STAGE_AT (2 * KT_B)           // 34816
#define ATTN_NS 3
#define ATTN_SMEM (ATTN_NS * STAGE_AT)  // 104448

__device__ __forceinline__ void load_kv_tile(
    uint32_t base, const __half* Kp, const __half* Vp, int bh, int kt, int tid)
{
    size_t gb = ((size_t)bh * S_ + (size_t)kt * 64) * HD_;
#pragma unroll
    for (int i = tid; i < 1024; i += 256) {
        int r = i >> 4, g = i & 15;
        uint32_t so = (uint32_t)(r * AT_STRIDE + g * 16);
        size_t go = gb + (size_t)r * HD_ + g * 8;
        CP_ASYNC16(base + so,        Kp + go);
        CP_ASYNC16(base + V_OFF + so, Vp + go);
    }
}

__global__ __launch_bounds__(256)
void attn_h(const __half* __restrict__ Qp, const __half* __restrict__ Kp,
            const __half* __restrict__ Vp, __half* __restrict__ Oa)
{
    extern __shared__ char sm[];
    const uint32_t smb = smem_u32(sm);
    const int tid  = threadIdx.x;
    const int wid  = tid >> 5;
    const int lane = tid & 31;
    const int grow = lane >> 2;
    const int gcol2 = (lane & 3) * 2;
    const int bh = blockIdx.y;
    const int iq = gridDim.x - 1 - blockIdx.x;      // heavy tiles first
    const int row0 = iq * 128 + wid * 16;

    // Q fragments straight from global
    uint32_t q[8][4];
    {
        const __half* qb = Qp + ((size_t)bh * S_ + row0) * HD_;
#pragma unroll
        for (int j = 0; j < 8; j++) {
            int c0 = j * 16 + gcol2;
            q[j][0] = *(const uint32_t*)(qb + (size_t)grow * HD_ + c0);
            q[j][1] = *(const uint32_t*)(qb + (size_t)(grow + 8) * HD_ + c0);
            q[j][2] = *(const uint32_t*)(qb + (size_t)grow * HD_ + c0 + 8);
            q[j][3] = *(const uint32_t*)(qb + (size_t)(grow + 8) * HD_ + c0 + 8);
        }
    }

    float o[16][4];
#pragma unroll
    for (int i = 0; i < 16; i++)
#pragma unroll
        for (int j = 0; j < 4; j++) o[i][j] = 0.f;
    float m0 = -1e30f, m1 = -1e30f, l0 = 0.f, l1 = 0.f;

    const int ktmax = 2 * iq + 1;

    load_kv_tile(smb, Kp, Vp, bh, 0, tid);
    CP_COMMIT();
    if (ktmax >= 1) load_kv_tile(smb + STAGE_AT, Kp, Vp, bh, 1, tid);
    CP_COMMIT();

    const int lrow = lane & 15;
    const int lcol = (lane >> 4) * 16;

    int stage = 0;
    for (int kt = 0; kt <= ktmax; kt++) {
        CP_WAIT1();
        __syncthreads();

        if (kt + 2 <= ktmax) {
            int ns = stage + 2; if (ns >= ATTN_NS) ns -= ATTN_NS;
            load_kv_tile(smb + (uint32_t)ns * STAGE_AT, Kp, Vp, bh, kt + 2, tid);
        }
        CP_COMMIT();

        const uint32_t stg = smb + (uint32_t)stage * STAGE_AT;
        const bool active = (kt * 64 <= row0 + 15);

        if (active) {
            // ---- S = Q K^T ----
            float s[8][4];
#pragma unroll
            for (int i = 0; i < 8; i++)
#pragma unroll
                for (int j = 0; j < 4; j++) s[i][j] = 0.f;

#pragma unroll
            for (int ks = 0; ks < 8; ks++) {
                uint32_t b[8][2];
#pragma unroll
                for (int nb = 0; nb < 4; nb++) {
                    uint32_t r0, r1, r2, r3;
                    uint32_t addr = stg +
                        (uint32_t)((nb * 16 + lrow) * AT_STRIDE + ks * 32 + lcol);
                    LDSM_X4(r0, r1, r2, r3, addr);
                    b[2 * nb][0] = r0; b[2 * nb][1] = r2;
                    b[2 * nb + 1][0] = r1; b[2 * nb + 1][1] = r3;
                }
#pragma unroll
                for (int nt = 0; nt < 8; nt++) MMAH(s[nt], q[ks], b[nt]);
            }

            // ---- causal mask ----
            if (kt * 64 + 63 > row0) {
                const int kb = kt * 64;
#pragma unroll
                for (int nt = 0; nt < 8; nt++) {
#pragma unroll
                    for (int e = 0; e < 4; e++) {
                        int col = kb + nt * 8 + gcol2 + (e & 1);
                        int row = row0 + grow + ((e >> 1) << 3);
                        if (col > row) s[nt][e] = -1e30f;
                    }
                }
            }

            // ---- online softmax (log2 domain) ----
            float ml0 = -1e30f, ml1 = -1e30f;
#pragma unroll
            for (int nt = 0; nt < 8; nt++) {
                ml0 = fmaxf(ml0, fmaxf(s[nt][0], s[nt][1]));
                ml1 = fmaxf(ml1, fmaxf(s[nt][2], s[nt][3]));
            }
#pragma unroll
            for (int d = 1; d < 4; d <<= 1) {
                ml0 = fmaxf(ml0, __shfl_xor_sync(0xFFFFFFFFu, ml0, d));
                ml1 = fmaxf(ml1, __shfl_xor_sync(0xFFFFFFFFu, ml1, d));
            }
            float mn0 = fmaxf(m0, ml0), mn1 = fmaxf(m1, ml1);
            float sc0 = ex2f(m0 - mn0), sc1 = ex2f(m1 - mn1);
            float sum0 = 0.f, sum1 = 0.f;
#pragma unroll
            for (int nt = 0; nt < 8; nt++) {
                s[nt][0] = ex2f(s[nt][0] - mn0);
                s[nt][1] = ex2f(s[nt][1] - mn0);
                s[nt][2] = ex2f(s[nt][2] - mn1);
                s[nt][3] = ex2f(s[nt][3] - mn1);
                sum0 += s[nt][0] + s[nt][1];
                sum1 += s[nt][2] + s[nt][3];
            }
#pragma unroll
            for (int d = 1; d < 4; d <<= 1) {
                sum0 += __shfl_xor_sync(0xFFFFFFFFu, sum0, d);
                sum1 += __shfl_xor_sync(0xFFFFFFFFu, sum1, d);
            }
            l0 = l0 * sc0 + sum0;
            l1 = l1 * sc1 + sum1;
            m0 = mn0; m1 = mn1;
#pragma unroll
            for (int nt = 0; nt < 16; nt++) {
                o[nt][0] *= sc0; o[nt][1] *= sc0;
                o[nt][2] *= sc1; o[nt][3] *= sc1;
            }

            // ---- pack P into fp16 A-fragments ----
            uint32_t pa[4][4];
#pragma unroll
            for (int j = 0; j < 4; j++) {
                pa[j][0] = pack_h2(s[2*j][0],   s[2*j][1]);
                pa[j][1] = pack_h2(s[2*j][2],   s[2*j][3]);
                pa[j][2] = pack_h2(s[2*j+1][0], s[2*j+1][1]);
                pa[j][3] = pack_h2(s[2*j+1][2], s[2*j+1][3]);
            }

            // ---- O += P V ----
#pragma unroll
            for (int ks4 = 0; ks4 < 4; ks4++) {
#pragma unroll
                for (int np = 0; np < 8; np++) {
                    uint32_t r0, r1, r2, r3;
                    uint32_t addr = stg + V_OFF +
                        (uint32_t)((ks4 * 16 + lrow) * AT_STRIDE + np * 32 + lcol);
                    LDSM_X4_T(r0, r1, r2, r3, addr);
                    uint32_t b0[2] = { r0, r1 }, b1[2] = { r2, r3 };
                    MMAH(o[2 * np],     pa[ks4], b0);
                    MMAH(o[2 * np + 1], pa[ks4], b1);
                }
            }
        }
        if (++stage == ATTN_NS) stage = 0;
    }

    // ---- epilogue: write fp16 directly into proj-GEMM A buffer ----
    const int b = bh >> 4, h = bh & 15;
    float inv0 = 1.f / l0, inv1 = 1.f / l1;
#pragma unroll
    for (int nt = 0; nt < 16; nt++) {
        int col = h * HD_ + nt * 8 + gcol2;
        __half* p0 = Oa + ((size_t)(b * S_ + row0 + grow)) * D_ + col;
        __half* p1 = Oa + ((size_t)(b * S_ + row0 + grow + 8)) * D_ + col;
        *(uint32_t*)p0 = pack_h2(o[nt][0] * inv0, o[nt][1] * inv0);
        *(uint32_t*)p1 = pack_h2(o[nt][2] * inv1, o[nt][3] * inv1);
    }
}

// ---------------- launch ----------------
extern "C" void kernel_launch(void* const* d_in, const int* in_sizes, int n_in,
                              void* d_out, int out_size)
{
    const float* x     = (const float*)d_in[0];
    // d_in[1] = mask (causal tril, handled analytically)
    const float* sinp  = (const float*)d_in[2];
    const float* cosp  = (const float*)d_in[3];
    const float* Wqkv  = (const float*)d_in[4];
    const float* Wproj = (const float*)d_in[5];
    float* out = (float*)d_out;

    __half *a16, *b16, *q16, *k16, *v16;
    cudaGetSymbolAddress((void**)&a16, g_a16);
    cudaGetSymbolAddress((void**)&b16, g_b16);
    cudaGetSymbolAddress((void**)&q16, g_q16);
    cudaGetSymbolAddress((void**)&k16, g_k16);
    cudaGetSymbolAddress((void**)&v16, g_v16);

    cudaFuncSetAttribute(gemm_h,   cudaFuncAttributeMaxDynamicSharedMemorySize, GEMM_SMEM);
    cudaFuncSetAttribute(gemm_qkv, cudaFuncAttributeMaxDynamicSharedMemorySize, GEMM_SMEM);
    cudaFuncSetAttribute(attn_h,   cudaFuncAttributeMaxDynamicSharedMemorySize, ATTN_SMEM);

    // 1) convert x and Wqkv to fp16
    conv16<<<(M_ * K_ / 4 + 255) / 256, 256>>>(x, a16, M_ * K_ / 4);
    conv_w_t16<<<dim3(N3_ / 32, K_ / 32), 256>>>(Wqkv, b16, K_, N3_);

    // 2) QKV projection + fused RoPE + head-major fp16 scatter
    gemm_qkv<<<dim3(N3_ / 256, M_ / 128), 512, GEMM_SMEM>>>(a16, b16, sinp, cosp,
                                                            q16, k16, v16);

    // 3) causal flash attention (tensor cores); writes proj A operand fp16
    attn_h<<<dim3(S_ / 128, B_ * H_), 256, ATTN_SMEM>>>(q16, k16, v16, a16);

    // 4) output projection (tensor cores)
    conv_w_t16<<<dim3(D_ / 32, K_ / 32), 256>>>(Wproj, b16, K_, D_);
    gemm_h<<<dim3(D_ / 256, M_ / 128), 512, GEMM_SMEM>>>(a16, b16, out, D_, K_);
}